// round 10
// baseline (speedup 1.0000x reference)
#include <cuda_runtime.h>
#include <cuda_fp16.h>
#include <math.h>
#include <stdint.h>

#define HIDDEN 1024
#define STATE  64
#define INTER  4096
#define BATCH  4
#define SEQ    2048
#define ROWS   (BATCH*SEQ)   // 8192
#define NCHUNK 32
#define CLEN   64            // NCHUNK*CLEN == SEQ

// ---------------- scratch (static device allocations; no cudaMalloc) ----------------
__device__ float  g_hn1[ROWS*HIDDEN];
__device__ __half g_hn1h[ROWS*HIDDEN];
__device__ float  g_h  [ROWS*HIDDEN];
__device__ __half g_hn2h[ROWS*HIDDEN];
__device__ float  g_U  [ROWS*STATE];
__device__ float  g_S  [ROWS*STATE];
__device__ __half g_Sh [ROWS*STATE];
__device__ __half g_acth[ROWS*INTER];     // silu(gate)*up (half)
__device__ __half g_Bbarh[128*HIDDEN];    // rows 64..127 stay zero (zero-init)
__device__ __half g_Ch[HIDDEN*STATE];
__device__ float  g_AbT [STATE*STATE];    // AbT[j*64+i] = A_bar[i][j]
__device__ float  g_A64T[STATE*STATE];
__device__ float  g_tail [BATCH*NCHUNK*STATE];
__device__ float  g_carry[BATCH*NCHUNK*STATE];
__device__ __half g_wgh[INTER*HIDDEN];    // fp16 weights
__device__ __half g_wuh[INTER*HIDDEN];
__device__ __half g_wdh[HIDDEN*INTER];

// ================= small-matrix helper: 2 rows x 4 cols per thread =================
__device__ __forceinline__ void mm64_24(const float* __restrict__ X,
                                        const float* __restrict__ Y,
                                        int i0, int j0, float v[8])
{
    #pragma unroll
    for (int c = 0; c < 8; c++) v[c] = 0.f;
    #pragma unroll
    for (int lb = 0; lb < 64; lb += 4) {
        float4 x0 = *(const float4*)&X[(i0+0)*64 + lb];
        float4 x1 = *(const float4*)&X[(i0+1)*64 + lb];
        float4 y0 = *(const float4*)&Y[(lb+0)*64 + j0];
        float4 y1 = *(const float4*)&Y[(lb+1)*64 + j0];
        float4 y2 = *(const float4*)&Y[(lb+2)*64 + j0];
        float4 y3 = *(const float4*)&Y[(lb+3)*64 + j0];
        v[0] += x0.x*y0.x + x0.y*y1.x + x0.z*y2.x + x0.w*y3.x;
        v[1] += x0.x*y0.y + x0.y*y1.y + x0.z*y2.y + x0.w*y3.y;
        v[2] += x0.x*y0.z + x0.y*y1.z + x0.z*y2.z + x0.w*y3.z;
        v[3] += x0.x*y0.w + x0.y*y1.w + x0.z*y2.w + x0.w*y3.w;
        v[4] += x1.x*y0.x + x1.y*y1.x + x1.z*y2.x + x1.w*y3.x;
        v[5] += x1.x*y0.y + x1.y*y1.y + x1.z*y2.y + x1.w*y3.y;
        v[6] += x1.x*y0.z + x1.y*y1.z + x1.z*y2.z + x1.w*y3.z;
        v[7] += x1.x*y0.w + x1.y*y1.w + x1.z*y2.w + x1.w*y3.w;
    }
}

// ---------------- prep (fused, 512 threads): dt, Bbar, expm, A^64 ----------------
__global__ void __launch_bounds__(512) prep_kernel(
    const float* __restrict__ A,
    const float* __restrict__ B,
    const float* __restrict__ log_dt)
{
    __shared__ __align__(16) float Mm[4096];
    __shared__ __align__(16) float Tb[4096];
    __shared__ __align__(16) float Rb[4096];
    int tid = threadIdx.x;                 // 512

    float local = 0.f;
    for (int e = tid; e < HIDDEN; e += 512) {
        float d = expf(log_dt[e]);
        Tb[e] = d;
        local += d;
    }
    Rb[tid] = local;
    __syncthreads();
    for (int s = 256; s > 0; s >>= 1) {
        if (tid < s) Rb[tid] += Rb[tid + s];
        __syncthreads();
    }
    float md = Rb[0] * (1.f / HIDDEN);

    for (int e = tid; e < STATE*HIDDEN; e += 512)
        g_Bbarh[e] = __float2half(B[e] * Tb[e & (HIDDEN - 1)]);
    __syncthreads();

    int i0 = (tid >> 4) * 2;
    int j0 = (tid & 15) * 4;

    for (int e = tid; e < 4096; e += 512) {
        float m = A[e] * md;
        Mm[e] = m; Tb[e] = m;
        Rb[e] = m + ((e >> 6) == (e & 63) ? 1.f : 0.f);
    }
    __syncthreads();

    for (int k = 2; k <= 5; k++) {
        float v[8];
        mm64_24(Tb, Mm, i0, j0, v);
        float inv = 1.f / (float)k;
        __syncthreads();
        #pragma unroll
        for (int r = 0; r < 2; r++)
            #pragma unroll
            for (int c = 0; c < 4; c++) {
                float nv = v[r*4 + c] * inv;
                Tb[(i0+r)*64 + j0 + c] = nv;
                Rb[(i0+r)*64 + j0 + c] += nv;
            }
        __syncthreads();
    }

    #pragma unroll
    for (int r = 0; r < 2; r++)
        #pragma unroll
        for (int c = 0; c < 4; c++)
            g_AbT[(j0+c)*64 + (i0+r)] = Rb[(i0+r)*64 + j0 + c];

    for (int s = 0; s < 6; s++) {
        float v[8];
        mm64_24(Rb, Rb, i0, j0, v);
        __syncthreads();
        #pragma unroll
        for (int r = 0; r < 2; r++)
            #pragma unroll
            for (int c = 0; c < 4; c++)
                Rb[(i0+r)*64 + j0 + c] = v[r*4 + c];
        __syncthreads();
    }
    #pragma unroll
    for (int r = 0; r < 2; r++)
        #pragma unroll
        for (int c = 0; c < 4; c++)
            g_A64T[(j0+c)*64 + (i0+r)] = Rb[(i0+r)*64 + j0 + c];
}

// ---------------- rmsnorm -> fp32 (+ optional fp16 mirror) ----------------
__global__ void rmsnorm_kernel(const float* __restrict__ x,
                               const float* __restrict__ w,
                               float* __restrict__ outf,
                               __half* __restrict__ outh)
{
    int row = blockIdx.x;
    const float4* xr = (const float4*)(x + (size_t)row * HIDDEN);
    float4 v = xr[threadIdx.x];
    float ss = v.x*v.x + v.y*v.y + v.z*v.z + v.w*v.w;
    #pragma unroll
    for (int o = 16; o > 0; o >>= 1) ss += __shfl_down_sync(0xffffffffu, ss, o);
    __shared__ float wr[8];
    __shared__ float sc;
    if ((threadIdx.x & 31) == 0) wr[threadIdx.x >> 5] = ss;
    __syncthreads();
    if (threadIdx.x == 0) {
        float t = 0.f;
        #pragma unroll
        for (int k = 0; k < 8; k++) t += wr[k];
        sc = rsqrtf(t * (1.f / HIDDEN) + 1e-6f);
    }
    __syncthreads();
    float s = sc;
    float4 wv = ((const float4*)w)[threadIdx.x];
    float4 o4 = make_float4(v.x*s*wv.x, v.y*s*wv.y, v.z*s*wv.z, v.w*s*wv.w);
    if (outf) ((float4*)(outf + (size_t)row * HIDDEN))[threadIdx.x] = o4;
    if (outh) {
        __half2* op = (__half2*)(outh + (size_t)row * HIDDEN) + threadIdx.x*2;
        op[0] = __floats2half2_rn(o4.x, o4.y);
        op[1] = __floats2half2_rn(o4.z, o4.w);
    }
}

// ---------------- fp32 -> fp16 conversion ----------------
__global__ void f2h_kernel(const float* __restrict__ in, __half* __restrict__ out, int n2)
{
    int i = blockIdx.x * 256 + threadIdx.x;
    int stride = gridDim.x * 256;
    const float2* in2 = (const float2*)in;
    __half2* out2 = (__half2*)out;
    for (; i < n2; i += stride) {
        float2 v = in2[i];
        out2[i] = __floats2half2_rn(v.x, v.y);
    }
}

// ---------------- chunked scan ----------------
__global__ void local_scan_kernel()
{
    int c = blockIdx.x, b = blockIdx.y;
    const float* u = g_U + (size_t)(b*SEQ + c*CLEN) * STATE;
    float* sout    = g_S + (size_t)(b*SEQ + c*CLEN) * STATE;

    __shared__ float st[64];
    __shared__ float part[4][64];
    __shared__ float ub[CLEN*64];

    int tid = threadIdx.x;
    int i = tid & 63, p = tid >> 6;

    float a[16];
    #pragma unroll
    for (int jj = 0; jj < 16; jj++) a[jj] = g_AbT[(p*16 + jj)*64 + i];

    for (int e = tid; e < CLEN*64; e += 256) ub[e] = u[e];
    if (tid < 64) st[i] = 0.f;
    __syncthreads();

    for (int t = 0; t < CLEN; t++) {
        float acc = 0.f;
        #pragma unroll
        for (int jj = 0; jj < 16; jj++) acc += a[jj] * st[p*16 + jj];
        part[p][i] = acc;
        __syncthreads();
        if (tid < 64) {
            float v = part[0][i] + part[1][i] + part[2][i] + part[3][i] + ub[t*64 + i];
            st[i] = v;
            sout[(size_t)t*STATE + i] = v;
        }
        __syncthreads();
    }
    if (tid < 64) g_tail[(size_t)(b*NCHUNK + c)*STATE + i] = st[i];
}

__global__ void carry_kernel()
{
    int b = blockIdx.x;
    __shared__ float st[64];
    __shared__ float part[4][64];
    __shared__ float tails[NCHUNK*64];

    int tid = threadIdx.x;
    int i = tid & 63, p = tid >> 6;

    float a[16];
    #pragma unroll
    for (int jj = 0; jj < 16; jj++) a[jj] = g_A64T[(p*16 + jj)*64 + i];

    for (int e = tid; e < NCHUNK*64; e += 256)
        tails[e] = g_tail[(size_t)b*NCHUNK*STATE + e];
    if (tid < 64) {
        st[i] = 0.f;
        g_carry[(size_t)b*NCHUNK*STATE + i] = 0.f;
    }
    __syncthreads();

    for (int c = 1; c < NCHUNK; c++) {
        float acc = 0.f;
        #pragma unroll
        for (int jj = 0; jj < 16; jj++) acc += a[jj] * st[p*16 + jj];
        part[p][i] = acc;
        __syncthreads();
        if (tid < 64) {
            float v = part[0][i] + part[1][i] + part[2][i] + part[3][i]
                    + tails[(c-1)*64 + i];
            st[i] = v;
            g_carry[(size_t)(b*NCHUNK + c)*STATE + i] = v;
        }
        __syncthreads();
    }
}

// fixup: S_final = S_local + A^{t+1} carry; writes HALF S for the tensor GEMM
__global__ void fixup_kernel()
{
    int c = blockIdx.x, b = blockIdx.y;
    const float* sin = g_S  + (size_t)(b*SEQ + c*CLEN) * STATE;
    __half* sout     = g_Sh + (size_t)(b*SEQ + c*CLEN) * STATE;

    __shared__ float st[64];
    __shared__ float part[4][64];

    int tid = threadIdx.x;
    int i = tid & 63, p = tid >> 6;

    float a[16];
    #pragma unroll
    for (int jj = 0; jj < 16; jj++) a[jj] = g_AbT[(p*16 + jj)*64 + i];

    if (tid < 64) st[i] = g_carry[(size_t)(b*NCHUNK + c)*STATE + i];
    __syncthreads();

    for (int t = 0; t < CLEN; t++) {
        float acc = 0.f;
        #pragma unroll
        for (int jj = 0; jj < 16; jj++) acc += a[jj] * st[p*16 + jj];
        part[p][i] = acc;
        __syncthreads();
        if (tid < 64) {
            float v = part[0][i] + part[1][i] + part[2][i] + part[3][i];
            st[i] = v;
            sout[(size_t)t*STATE + i] = __float2half(v + sin[(size_t)t*STATE + i]);
        }
        __syncthreads();
    }
}

// ================= fp16 tensor-core GEMM (R7 v3): C = A[M,K] @ B[N,K]^T =================
__device__ __forceinline__ void ldsm4(uint32_t& r0, uint32_t& r1,
                                      uint32_t& r2, uint32_t& r3, uint32_t addr)
{
    asm volatile("ldmatrix.sync.aligned.m8n8.x4.shared.b16 {%0,%1,%2,%3}, [%4];"
                 : "=r"(r0), "=r"(r1), "=r"(r2), "=r"(r3) : "r"(addr));
}
__device__ __forceinline__ void cp16s(uint32_t saddr, const void* g)
{
    asm volatile("cp.async.cg.shared.global [%0], [%1], 16;" :: "r"(saddr), "l"(g));
}
__device__ __forceinline__ void mma_f16(float* d, const uint32_t a[4],
                                        uint32_t b0, uint32_t b1)
{
    asm volatile(
        "mma.sync.aligned.m16n8k16.row.col.f32.f16.f16.f32 "
        "{%0,%1,%2,%3}, {%4,%5,%6,%7}, {%8,%9}, {%0,%1,%2,%3};\n"
        : "+f"(d[0]), "+f"(d[1]), "+f"(d[2]), "+f"(d[3])
        : "r"(a[0]), "r"(a[1]), "r"(a[2]), "r"(a[3]), "r"(b0), "r"(b1));
}

#define STAGE_B 20480        // bytes per stage (A 10240 + B 10240), row pitch 80B
#define TCSMEM  (3*STAGE_B)  // 61440

// modes: 0 outf=acc; 1 outf = res + acc + dvec[col]*extra; 3 outf = res + acc
__global__ void __launch_bounds__(256) gemm_f16(
    const __half* __restrict__ A, const __half* __restrict__ Bm,
    int M, int N, int K, float* __restrict__ outf,
    int mode, const float* __restrict__ res,
    const float* __restrict__ extra, const float* __restrict__ dvec)
{
    extern __shared__ __align__(16) char smem[];
    uint32_t smBase = (uint32_t)__cvta_generic_to_shared(smem);
    int tid = threadIdx.x;
    int m0 = blockIdx.y * 128, n0 = blockIdx.x * 128;

    int lr = tid >> 1, lc = (tid & 1) * 2;
    const __half* Ag = A  + (size_t)(m0 + lr) * K + lc*8;
    const __half* Bg = Bm + (size_t)(n0 + lr) * K + lc*8;
    uint32_t aDst = smBase + lr*80 + lc*16;
    uint32_t bDst = smBase + 10240 + lr*80 + lc*16;

    int lane = tid & 31, warp = tid >> 5;
    int wm = warp & 1, wn = warp >> 1;
    int gid = lane >> 2, tig = lane & 3;

    uint32_t aFrag = smBase
        + (uint32_t)(wm*64 + (lane & 7) + ((lane >> 3) & 1)*8) * 80
        + ((lane >> 4) & 1) * 16;
    uint32_t bFrag = smBase + 10240
        + (uint32_t)(wn*32 + ((lane >> 4) & 1)*8 + (lane & 7)) * 80
        + ((lane >> 3) & 1) * 16;

    float acc[4][4][4];
    #pragma unroll
    for (int mt = 0; mt < 4; mt++)
        #pragma unroll
        for (int nt = 0; nt < 4; nt++)
            #pragma unroll
            for (int r = 0; r < 4; r++) acc[mt][nt][r] = 0.f;

    int NT = K >> 5;

    #define LOAD_STAGE(kt, s) do {                                           \
        uint32_t off_ = (uint32_t)(s) * STAGE_B;                             \
        const __half* ga_ = Ag + (size_t)(kt)*32;                            \
        const __half* gb_ = Bg + (size_t)(kt)*32;                            \
        cp16s(aDst + off_,      ga_);                                        \
        cp16s(aDst + off_ + 16, ga_ + 8);                                    \
        cp16s(bDst + off_,      gb_);                                        \
        cp16s(bDst + off_ + 16, gb_ + 8);                                    \
        asm volatile("cp.async.commit_group;\n");                            \
    } while (0)

    LOAD_STAGE(0, 0);
    if (NT > 1) LOAD_STAGE(1, 1);

    int st = 0, ld = 2;
    for (int kt = 0; kt < NT; kt++) {
        if (kt + 1 < NT) asm volatile("cp.async.wait_group 1;\n");
        else             asm volatile("cp.async.wait_group 0;\n");
        __syncthreads();

        if (kt + 2 < NT) {
            LOAD_STAGE(kt + 2, ld);
            ld = (ld == 2) ? 0 : ld + 1;
        }

        uint32_t soff = (uint32_t)st * STAGE_B;
        st = (st == 2) ? 0 : st + 1;

        #pragma unroll
        for (int ks = 0; ks < 2; ks++) {
            uint32_t bb[2][4];
            #pragma unroll
            for (int p = 0; p < 2; p++)
                ldsm4(bb[p][0], bb[p][1], bb[p][2], bb[p][3],
                      bFrag + soff + (uint32_t)p*16*80 + ks*32);
            #pragma unroll
            for (int mt = 0; mt < 4; mt++) {
                uint32_t aa[4];
                ldsm4(aa[0], aa[1], aa[2], aa[3],
                      aFrag + soff + (uint32_t)mt*16*80 + ks*32);
                mma_f16(acc[mt][0], aa, bb[0][0], bb[0][1]);
                mma_f16(acc[mt][1], aa, bb[0][2], bb[0][3]);
                mma_f16(acc[mt][2], aa, bb[1][0], bb[1][1]);
                mma_f16(acc[mt][3], aa, bb[1][2], bb[1][3]);
            }
        }
    }
    #undef LOAD_STAGE

    #pragma unroll
    for (int mt = 0; mt < 4; mt++) {
        #pragma unroll
        for (int nt = 0; nt < 4; nt++) {
            int row0 = m0 + wm*64 + mt*16 + gid;
            int col0 = n0 + wn*32 + nt*8 + tig*2;
            if (col0 >= N) continue;
            #pragma unroll
            for (int half = 0; half < 2; half++) {
                int row = row0 + half*8;
                size_t idx = (size_t)row * N + col0;
                float v0 = acc[mt][nt][half*2 + 0];
                float v1 = acc[mt][nt][half*2 + 1];
                if (mode == 1) {
                    float2 r2 = *(const float2*)(res + idx);
                    float2 e2 = *(const float2*)(extra + idx);
                    v0 = r2.x + v0 + dvec[col0]   * e2.x;
                    v1 = r2.y + v1 + dvec[col0+1] * e2.y;
                    *(float2*)(outf + idx) = make_float2(v0, v1);
                } else if (mode == 3) {
                    float2 r2 = *(const float2*)(res + idx);
                    *(float2*)(outf + idx) = make_float2(v0 + r2.x, v1 + r2.y);
                } else {
                    *(float2*)(outf + idx) = make_float2(v0, v1);
                }
            }
        }
    }
}

// ================= fused gate+up GEMM: acth = silu(hn2@wg^T) * (hn2@wu^T) =================
// B smem rows interleaved: row 2j = wg[nb*64+j], row 2j+1 = wu[nb*64+j].
// Output fragment (d0,d1) at even col0 = (gate[j], up[j]), j = col0/2.
__global__ void __launch_bounds__(256) gemm_gateup(
    const __half* __restrict__ A, const __half* __restrict__ Wg,
    const __half* __restrict__ Wu, int M, int K, __half* __restrict__ outh)
{
    extern __shared__ __align__(16) char smem[];
    uint32_t smBase = (uint32_t)__cvta_generic_to_shared(smem);
    int tid = threadIdx.x;
    int m0 = blockIdx.y * 128;
    int nb = blockIdx.x;                   // 64-wide gate/up column block

    int lr = tid >> 1, lc = (tid & 1) * 2;
    const __half* Ag = A + (size_t)(m0 + lr) * K + lc*8;
    const __half* Wsrc = (lr & 1) ? Wu : Wg;
    const __half* Bg = Wsrc + (size_t)(nb*64 + (lr >> 1)) * K + lc*8;
    uint32_t aDst = smBase + lr*80 + lc*16;
    uint32_t bDst = smBase + 10240 + lr*80 + lc*16;

    int lane = tid & 31, warp = tid >> 5;
    int wm = warp & 1, wn = warp >> 1;
    int gid = lane >> 2, tig = lane & 3;

    uint32_t aFrag = smBase
        + (uint32_t)(wm*64 + (lane & 7) + ((lane >> 3) & 1)*8) * 80
        + ((lane >> 4) & 1) * 16;
    uint32_t bFrag = smBase + 10240
        + (uint32_t)(wn*32 + ((lane >> 4) & 1)*8 + (lane & 7)) * 80
        + ((lane >> 3) & 1) * 16;

    float acc[4][4][4];
    #pragma unroll
    for (int mt = 0; mt < 4; mt++)
        #pragma unroll
        for (int nt = 0; nt < 4; nt++)
            #pragma unroll
            for (int r = 0; r < 4; r++) acc[mt][nt][r] = 0.f;

    int NT = K >> 5;

    #define LOAD_STAGE(kt, s) do {                                           \
        uint32_t off_ = (uint32_t)(s) * STAGE_B;                             \
        const __half* ga_ = Ag + (size_t)(kt)*32;                            \
        const __half* gb_ = Bg + (size_t)(kt)*32;                            \
        cp16s(aDst + off_,      ga_);                                        \
        cp16s(aDst + off_ + 16, ga_ + 8);                                    \
        cp16s(bDst + off_,      gb_);                                        \
        cp16s(bDst + off_ + 16, gb_ + 8);                                    \
        asm volatile("cp.async.commit_group;\n");                            \
    } while (0)

    LOAD_STAGE(0, 0);
    if (NT > 1) LOAD_STAGE(1, 1);

    int st = 0, ld = 2;
    for (int kt = 0; kt < NT; kt++) {
        if (kt + 1 < NT) asm volatile("cp.async.wait_group 1;\n");
        else             asm volatile("cp.async.wait_group 0;\n");
        __syncthreads();

        if (kt + 2 < NT) {
            LOAD_STAGE(kt + 2, ld);
            ld = (ld == 2) ? 0 : ld + 1;
        }

        uint32_t soff = (uint32_t)st * STAGE_B;
        st = (st == 2) ? 0 : st + 1;

        #pragma unroll
        for (int ks = 0; ks < 2; ks++) {
            uint32_t bb[2][4];
            #pragma unroll
            for (int p = 0; p < 2; p++)
                ldsm4(bb[p][0], bb[p][1], bb[p][2], bb[p][3],
                      bFrag + soff + (uint32_t)p*16*80 + ks*32);
            #pragma unroll
            for (int mt = 0; mt < 4; mt++) {
                uint32_t aa[4];
                ldsm4(aa[0], aa[1], aa[2], aa[3],
                      aFrag + soff + (uint32_t)mt*16*80 + ks*32);
                mma_f16(acc[mt][0], aa, bb[0][0], bb[0][1]);
                mma_f16(acc[mt][1], aa, bb[0][2], bb[0][3]);
                mma_f16(acc[mt][2], aa, bb[1][0], bb[1][1]);
                mma_f16(acc[mt][3], aa, bb[1][2], bb[1][3]);
            }
        }
    }
    #undef LOAD_STAGE

    // epilogue: d0 = gate, d1 = up at output col nb*64 + col0/2
    #pragma unroll
    for (int mt = 0; mt < 4; mt++) {
        #pragma unroll
        for (int nt = 0; nt < 4; nt++) {
            int row0 = m0 + wm*64 + mt*16 + gid;
            int col0 = wn*32 + nt*8 + tig*2;   // even
            int j = nb*64 + (col0 >> 1);
            #pragma unroll
            for (int half = 0; half < 2; half++) {
                int row = row0 + half*8;
                float gg = acc[mt][nt][half*2 + 0];
                float uu = acc[mt][nt][half*2 + 1];
                float val = uu * (gg / (1.f + __expf(-gg)));
                outh[(size_t)row * INTER + j] = __float2half(val);
            }
        }
    }
}

// ---------------- launch ----------------
extern "C" void kernel_launch(void* const* d_in, const int* in_sizes, int n_in,
                              void* d_out, int out_size)
{
    const float* x      = (const float*)d_in[0];
    const float* A      = (const float*)d_in[1];
    const float* B      = (const float*)d_in[2];
    const float* C      = (const float*)d_in[3];
    const float* D      = (const float*)d_in[4];
    const float* log_dt = (const float*)d_in[5];
    const float* w_gate = (const float*)d_in[6];
    const float* w_up   = (const float*)d_in[7];
    const float* w_down = (const float*)d_in[8];
    const float* ln1    = (const float*)d_in[9];
    const float* ln2    = (const float*)d_in[10];
    float* out = (float*)d_out;

    float *hn1, *h, *U;
    __half *hn1h, *hn2h, *acth, *Bbarh, *Ch, *Sh, *wgh, *wuh, *wdh;
    cudaGetSymbolAddress((void**)&hn1,   g_hn1);
    cudaGetSymbolAddress((void**)&hn1h,  g_hn1h);
    cudaGetSymbolAddress((void**)&h,     g_h);
    cudaGetSymbolAddress((void**)&hn2h,  g_hn2h);
    cudaGetSymbolAddress((void**)&U,     g_U);
    cudaGetSymbolAddress((void**)&acth,  g_acth);
    cudaGetSymbolAddress((void**)&Bbarh, g_Bbarh);
    cudaGetSymbolAddress((void**)&Ch,    g_Ch);
    cudaGetSymbolAddress((void**)&Sh,    g_Sh);
    cudaGetSymbolAddress((void**)&wgh,   g_wgh);
    cudaGetSymbolAddress((void**)&wuh,   g_wuh);
    cudaGetSymbolAddress((void**)&wdh,   g_wdh);

    cudaFuncSetAttribute(gemm_f16,    cudaFuncAttributeMaxDynamicSharedMemorySize, TCSMEM);
    cudaFuncSetAttribute(gemm_gateup, cudaFuncAttributeMaxDynamicSharedMemorySize, TCSMEM);

    // conversions (independent of SSM path)
    f2h_kernel<<<1024, 256>>>(w_gate, wgh, INTER*HIDDEN/2);
    f2h_kernel<<<1024, 256>>>(w_up,   wuh, INTER*HIDDEN/2);
    f2h_kernel<<<1024, 256>>>(w_down, wdh, HIDDEN*INTER/2);
    f2h_kernel<<<64, 256>>>(C, Ch, HIDDEN*STATE/2);

    // SSM path
    prep_kernel<<<1, 512>>>(A, B, log_dt);
    rmsnorm_kernel<<<ROWS, 256>>>(x, ln1, hn1, hn1h);
    gemm_f16<<<dim3(1, ROWS/128), 256, TCSMEM>>>(hn1h, Bbarh, ROWS, STATE, HIDDEN,
                                                 U, 0, nullptr, nullptr, nullptr);
    local_scan_kernel<<<dim3(NCHUNK, BATCH), 256>>>();
    carry_kernel<<<BATCH, 256>>>();
    fixup_kernel<<<dim3(NCHUNK, BATCH), 256>>>();
    // h = x + S @ C^T + D*hn1
    gemm_f16<<<dim3(HIDDEN/128, ROWS/128), 256, TCSMEM>>>(Sh, Ch, ROWS, HIDDEN, STATE,
                                                          h, 1, x, hn1, D);
    // FFN
    rmsnorm_kernel<<<ROWS, 256>>>(h, ln2, nullptr, hn2h);
    gemm_gateup<<<dim3(INTER/64, ROWS/128), 256, TCSMEM>>>(hn2h, wgh, wuh, ROWS, HIDDEN, acth);
    gemm_f16<<<dim3(HIDDEN/128, ROWS/128), 256, TCSMEM>>>(acth, wdh, ROWS, HIDDEN, INTER,
                                                          out, 3, h, nullptr, nullptr);
}

// round 13
// speedup vs baseline: 1.4295x; 1.4295x over previous
#include <cuda_runtime.h>
#include <cuda_fp16.h>
#include <math.h>
#include <stdint.h>

#define HIDDEN 1024
#define STATE  64
#define INTER  4096
#define BATCH  4
#define SEQ    2048
#define ROWS   (BATCH*SEQ)   // 8192
#define NCHUNK 32
#define CLEN   64            // NCHUNK*CLEN == SEQ

// ---------------- scratch (static device allocations; no cudaMalloc) ----------------
__device__ float  g_hn1[ROWS*HIDDEN];
__device__ __half g_hn1h[ROWS*HIDDEN];
__device__ float  g_h  [ROWS*HIDDEN];
__device__ __half g_hn2h[ROWS*HIDDEN];
__device__ float  g_U  [ROWS*STATE];
__device__ float  g_S  [ROWS*STATE];
__device__ __half g_Sh [ROWS*STATE];
__device__ __half g_gateh[ROWS*INTER];    // gate pre-activation (half)
__device__ __half g_acth[ROWS*INTER];     // silu(gate)*up (half)
__device__ __half g_Bbarh[128*HIDDEN];    // rows 64..127 stay zero (zero-init)
__device__ __half g_Ch[HIDDEN*STATE];
__device__ float  g_AbT [STATE*STATE];    // AbT[j*64+i] = A_bar[i][j]
__device__ float  g_A64T[STATE*STATE];
__device__ float  g_tail [BATCH*NCHUNK*STATE];
__device__ float  g_carry[BATCH*NCHUNK*STATE];
__device__ __half g_wgh[INTER*HIDDEN];    // fp16 weights
__device__ __half g_wuh[INTER*HIDDEN];
__device__ __half g_wdh[HIDDEN*INTER];

// ================= small-matrix helper: 2 rows x 4 cols per thread =================
__device__ __forceinline__ void mm64_24(const float* __restrict__ X,
                                        const float* __restrict__ Y,
                                        int i0, int j0, float v[8])
{
    #pragma unroll
    for (int c = 0; c < 8; c++) v[c] = 0.f;
    #pragma unroll
    for (int lb = 0; lb < 64; lb += 4) {
        float4 x0 = *(const float4*)&X[(i0+0)*64 + lb];
        float4 x1 = *(const float4*)&X[(i0+1)*64 + lb];
        float4 y0 = *(const float4*)&Y[(lb+0)*64 + j0];
        float4 y1 = *(const float4*)&Y[(lb+1)*64 + j0];
        float4 y2 = *(const float4*)&Y[(lb+2)*64 + j0];
        float4 y3 = *(const float4*)&Y[(lb+3)*64 + j0];
        v[0] += x0.x*y0.x + x0.y*y1.x + x0.z*y2.x + x0.w*y3.x;
        v[1] += x0.x*y0.y + x0.y*y1.y + x0.z*y2.y + x0.w*y3.y;
        v[2] += x0.x*y0.z + x0.y*y1.z + x0.z*y2.z + x0.w*y3.z;
        v[3] += x0.x*y0.w + x0.y*y1.w + x0.z*y2.w + x0.w*y3.w;
        v[4] += x1.x*y0.x + x1.y*y1.x + x1.z*y2.x + x1.w*y3.x;
        v[5] += x1.x*y0.y + x1.y*y1.y + x1.z*y2.y + x1.w*y3.y;
        v[6] += x1.x*y0.z + x1.y*y1.z + x1.z*y2.z + x1.w*y3.z;
        v[7] += x1.x*y0.w + x1.y*y1.w + x1.z*y2.w + x1.w*y3.w;
    }
}

// ---------------- prep (fused, 512 threads): dt, Bbar, expm, A^64 ----------------
__global__ void __launch_bounds__(512) prep_kernel(
    const float* __restrict__ A,
    const float* __restrict__ B,
    const float* __restrict__ log_dt)
{
    __shared__ __align__(16) float Mm[4096];
    __shared__ __align__(16) float Tb[4096];
    __shared__ __align__(16) float Rb[4096];
    int tid = threadIdx.x;                 // 512

    float local = 0.f;
    for (int e = tid; e < HIDDEN; e += 512) {
        float d = expf(log_dt[e]);
        Tb[e] = d;
        local += d;
    }
    Rb[tid] = local;
    __syncthreads();
    for (int s = 256; s > 0; s >>= 1) {
        if (tid < s) Rb[tid] += Rb[tid + s];
        __syncthreads();
    }
    float md = Rb[0] * (1.f / HIDDEN);

    for (int e = tid; e < STATE*HIDDEN; e += 512)
        g_Bbarh[e] = __float2half(B[e] * Tb[e & (HIDDEN - 1)]);
    __syncthreads();

    int i0 = (tid >> 4) * 2;
    int j0 = (tid & 15) * 4;

    for (int e = tid; e < 4096; e += 512) {
        float m = A[e] * md;
        Mm[e] = m; Tb[e] = m;
        Rb[e] = m + ((e >> 6) == (e & 63) ? 1.f : 0.f);
    }
    __syncthreads();

    for (int k = 2; k <= 5; k++) {
        float v[8];
        mm64_24(Tb, Mm, i0, j0, v);
        float inv = 1.f / (float)k;
        __syncthreads();
        #pragma unroll
        for (int r = 0; r < 2; r++)
            #pragma unroll
            for (int c = 0; c < 4; c++) {
                float nv = v[r*4 + c] * inv;
                Tb[(i0+r)*64 + j0 + c] = nv;
                Rb[(i0+r)*64 + j0 + c] += nv;
            }
        __syncthreads();
    }

    #pragma unroll
    for (int r = 0; r < 2; r++)
        #pragma unroll
        for (int c = 0; c < 4; c++)
            g_AbT[(j0+c)*64 + (i0+r)] = Rb[(i0+r)*64 + j0 + c];

    for (int s = 0; s < 6; s++) {
        float v[8];
        mm64_24(Rb, Rb, i0, j0, v);
        __syncthreads();
        #pragma unroll
        for (int r = 0; r < 2; r++)
            #pragma unroll
            for (int c = 0; c < 4; c++)
                Rb[(i0+r)*64 + j0 + c] = v[r*4 + c];
        __syncthreads();
    }
    #pragma unroll
    for (int r = 0; r < 2; r++)
        #pragma unroll
        for (int c = 0; c < 4; c++)
            g_A64T[(j0+c)*64 + (i0+r)] = Rb[(i0+r)*64 + j0 + c];
}

// ---------------- rmsnorm -> fp32 (+ optional fp16 mirror) ----------------
__global__ void rmsnorm_kernel(const float* __restrict__ x,
                               const float* __restrict__ w,
                               float* __restrict__ outf,
                               __half* __restrict__ outh)
{
    int row = blockIdx.x;
    const float4* xr = (const float4*)(x + (size_t)row * HIDDEN);
    float4 v = xr[threadIdx.x];
    float ss = v.x*v.x + v.y*v.y + v.z*v.z + v.w*v.w;
    #pragma unroll
    for (int o = 16; o > 0; o >>= 1) ss += __shfl_down_sync(0xffffffffu, ss, o);
    __shared__ float wr[8];
    __shared__ float sc;
    if ((threadIdx.x & 31) == 0) wr[threadIdx.x >> 5] = ss;
    __syncthreads();
    if (threadIdx.x == 0) {
        float t = 0.f;
        #pragma unroll
        for (int k = 0; k < 8; k++) t += wr[k];
        sc = rsqrtf(t * (1.f / HIDDEN) + 1e-6f);
    }
    __syncthreads();
    float s = sc;
    float4 wv = ((const float4*)w)[threadIdx.x];
    float4 o4 = make_float4(v.x*s*wv.x, v.y*s*wv.y, v.z*s*wv.z, v.w*s*wv.w);
    if (outf) ((float4*)(outf + (size_t)row * HIDDEN))[threadIdx.x] = o4;
    if (outh) {
        __half2* op = (__half2*)(outh + (size_t)row * HIDDEN) + threadIdx.x*2;
        op[0] = __floats2half2_rn(o4.x, o4.y);
        op[1] = __floats2half2_rn(o4.z, o4.w);
    }
}

// ---------------- fp32 -> fp16 conversion: all three FFN weights in one launch ----------------
__global__ void f2h_weights_kernel(const float* __restrict__ wg,
                                   const float* __restrict__ wu,
                                   const float* __restrict__ wd)
{
    int i = blockIdx.x * 256 + threadIdx.x;
    int stride = gridDim.x * 256;
    const int n2 = INTER*HIDDEN/2;
    const float2* g2 = (const float2*)wg;
    const float2* u2 = (const float2*)wu;
    const float2* d2 = (const float2*)wd;
    __half2* go = (__half2*)g_wgh;
    __half2* uo = (__half2*)g_wuh;
    __half2* dd = (__half2*)g_wdh;
    for (; i < n2; i += stride) {
        float2 a = g2[i]; go[i] = __floats2half2_rn(a.x, a.y);
        float2 b = u2[i]; uo[i] = __floats2half2_rn(b.x, b.y);
        float2 c = d2[i]; dd[i] = __floats2half2_rn(c.x, c.y);
    }
}

__global__ void f2h_kernel(const float* __restrict__ in, __half* __restrict__ out, int n2)
{
    int i = blockIdx.x * 256 + threadIdx.x;
    int stride = gridDim.x * 256;
    const float2* in2 = (const float2*)in;
    __half2* out2 = (__half2*)out;
    for (; i < n2; i += stride) {
        float2 v = in2[i];
        out2[i] = __floats2half2_rn(v.x, v.y);
    }
}

// ---------------- chunked scan ----------------
__global__ void local_scan_kernel()
{
    int c = blockIdx.x, b = blockIdx.y;
    const float* u = g_U + (size_t)(b*SEQ + c*CLEN) * STATE;
    float* sout    = g_S + (size_t)(b*SEQ + c*CLEN) * STATE;

    __shared__ float st[64];
    __shared__ float part[4][64];
    __shared__ float ub[CLEN*64];

    int tid = threadIdx.x;
    int i = tid & 63, p = tid >> 6;

    float a[16];
    #pragma unroll
    for (int jj = 0; jj < 16; jj++) a[jj] = g_AbT[(p*16 + jj)*64 + i];

    for (int e = tid; e < CLEN*64; e += 256) ub[e] = u[e];
    if (tid < 64) st[i] = 0.f;
    __syncthreads();

    for (int t = 0; t < CLEN; t++) {
        float acc = 0.f;
        #pragma unroll
        for (int jj = 0; jj < 16; jj++) acc += a[jj] * st[p*16 + jj];
        part[p][i] = acc;
        __syncthreads();
        if (tid < 64) {
            float v = part[0][i] + part[1][i] + part[2][i] + part[3][i] + ub[t*64 + i];
            st[i] = v;
            sout[(size_t)t*STATE + i] = v;
        }
        __syncthreads();
    }
    if (tid < 64) g_tail[(size_t)(b*NCHUNK + c)*STATE + i] = st[i];
}

__global__ void carry_kernel()
{
    int b = blockIdx.x;
    __shared__ float st[64];
    __shared__ float part[4][64];
    __shared__ float tails[NCHUNK*64];

    int tid = threadIdx.x;
    int i = tid & 63, p = tid >> 6;

    float a[16];
    #pragma unroll
    for (int jj = 0; jj < 16; jj++) a[jj] = g_A64T[(p*16 + jj)*64 + i];

    for (int e = tid; e < NCHUNK*64; e += 256)
        tails[e] = g_tail[(size_t)b*NCHUNK*STATE + e];
    if (tid < 64) {
        st[i] = 0.f;
        g_carry[(size_t)b*NCHUNK*STATE + i] = 0.f;
    }
    __syncthreads();

    for (int c = 1; c < NCHUNK; c++) {
        float acc = 0.f;
        #pragma unroll
        for (int jj = 0; jj < 16; jj++) acc += a[jj] * st[p*16 + jj];
        part[p][i] = acc;
        __syncthreads();
        if (tid < 64) {
            float v = part[0][i] + part[1][i] + part[2][i] + part[3][i]
                    + tails[(c-1)*64 + i];
            st[i] = v;
            g_carry[(size_t)(b*NCHUNK + c)*STATE + i] = v;
        }
        __syncthreads();
    }
}

// fixup: S_final = S_local + A^{t+1} carry; writes HALF S for the tensor GEMM
__global__ void fixup_kernel()
{
    int c = blockIdx.x, b = blockIdx.y;
    const float* sin = g_S  + (size_t)(b*SEQ + c*CLEN) * STATE;
    __half* sout     = g_Sh + (size_t)(b*SEQ + c*CLEN) * STATE;

    __shared__ float st[64];
    __shared__ float part[4][64];

    int tid = threadIdx.x;
    int i = tid & 63, p = tid >> 6;

    float a[16];
    #pragma unroll
    for (int jj = 0; jj < 16; jj++) a[jj] = g_AbT[(p*16 + jj)*64 + i];

    if (tid < 64) st[i] = g_carry[(size_t)(b*NCHUNK + c)*STATE + i];
    __syncthreads();

    for (int t = 0; t < CLEN; t++) {
        float acc = 0.f;
        #pragma unroll
        for (int jj = 0; jj < 16; jj++) acc += a[jj] * st[p*16 + jj];
        part[p][i] = acc;
        __syncthreads();
        if (tid < 64) {
            float v = part[0][i] + part[1][i] + part[2][i] + part[3][i];
            st[i] = v;
            sout[(size_t)t*STATE + i] = __float2half(v + sin[(size_t)t*STATE + i]);
        }
        __syncthreads();
    }
}

// ================= fp16 tensor-core GEMM (R7 v3): C = A[M,K] @ B[N,K]^T =================
__device__ __forceinline__ void ldsm4(uint32_t& r0, uint32_t& r1,
                                      uint32_t& r2, uint32_t& r3, uint32_t addr)
{
    asm volatile("ldmatrix.sync.aligned.m8n8.x4.shared.b16 {%0,%1,%2,%3}, [%4];"
                 : "=r"(r0), "=r"(r1), "=r"(r2), "=r"(r3) : "r"(addr));
}
__device__ __forceinline__ void cp16s(uint32_t saddr, const void* g)
{
    asm volatile("cp.async.cg.shared.global [%0], [%1], 16;" :: "r"(saddr), "l"(g));
}
__device__ __forceinline__ void mma_f16(float* d, const uint32_t a[4],
                                        uint32_t b0, uint32_t b1)
{
    asm volatile(
        "mma.sync.aligned.m16n8k16.row.col.f32.f16.f16.f32 "
        "{%0,%1,%2,%3}, {%4,%5,%6,%7}, {%8,%9}, {%0,%1,%2,%3};\n"
        : "+f"(d[0]), "+f"(d[1]), "+f"(d[2]), "+f"(d[3])
        : "r"(a[0]), "r"(a[1]), "r"(a[2]), "r"(a[3]), "r"(b0), "r"(b1));
}

#define STAGE_B 20480        // bytes per stage (A 10240 + B 10240), row pitch 80B
#define TCSMEM  (3*STAGE_B)  // 61440

// modes: 0 outf=acc; 1 outf = res + acc + dvec[col]*extra;
//        2 outh = half(silu(resh)*acc); 3 outf = res + acc; 4 outh = half(acc)
__global__ void __launch_bounds__(256) gemm_f16(
    const __half* __restrict__ A, const __half* __restrict__ Bm,
    int M, int N, int K, float* __restrict__ outf, __half* __restrict__ outh,
    int mode, const float* __restrict__ res, const __half* __restrict__ resh,
    const float* __restrict__ extra, const float* __restrict__ dvec)
{
    extern __shared__ __align__(16) char smem[];
    uint32_t smBase = (uint32_t)__cvta_generic_to_shared(smem);
    int tid = threadIdx.x;
    int m0 = blockIdx.y * 128, n0 = blockIdx.x * 128;

    int lr = tid >> 1, lc = (tid & 1) * 2;
    const __half* Ag = A  + (size_t)(m0 + lr) * K + lc*8;
    const __half* Bg = Bm + (size_t)(n0 + lr) * K + lc*8;
    uint32_t aDst = smBase + lr*80 + lc*16;
    uint32_t bDst = smBase + 10240 + lr*80 + lc*16;

    int lane = tid & 31, warp = tid >> 5;
    int wm = warp & 1, wn = warp >> 1;
    int gid = lane >> 2, tig = lane & 3;

    uint32_t aFrag = smBase
        + (uint32_t)(wm*64 + (lane & 7) + ((lane >> 3) & 1)*8) * 80
        + ((lane >> 4) & 1) * 16;
    uint32_t bFrag = smBase + 10240
        + (uint32_t)(wn*32 + ((lane >> 4) & 1)*8 + (lane & 7)) * 80
        + ((lane >> 3) & 1) * 16;

    float acc[4][4][4];
    #pragma unroll
    for (int mt = 0; mt < 4; mt++)
        #pragma unroll
        for (int nt = 0; nt < 4; nt++)
            #pragma unroll
            for (int r = 0; r < 4; r++) acc[mt][nt][r] = 0.f;

    int NT = K >> 5;

    #define LOAD_STAGE(kt, s) do {                                           \
        uint32_t off_ = (uint32_t)(s) * STAGE_B;                             \
        const __half* ga_ = Ag + (size_t)(kt)*32;                            \
        const __half* gb_ = Bg + (size_t)(kt)*32;                            \
        cp16s(aDst + off_,      ga_);                                        \
        cp16s(aDst + off_ + 16, ga_ + 8);                                    \
        cp16s(bDst + off_,      gb_);                                        \
        cp16s(bDst + off_ + 16, gb_ + 8);                                    \
        asm volatile("cp.async.commit_group;\n");                            \
    } while (0)

    LOAD_STAGE(0, 0);
    if (NT > 1) LOAD_STAGE(1, 1);

    int st = 0, ld = 2;
    for (int kt = 0; kt < NT; kt++) {
        if (kt + 1 < NT) asm volatile("cp.async.wait_group 1;\n");
        else             asm volatile("cp.async.wait_group 0;\n");
        __syncthreads();

        if (kt + 2 < NT) {
            LOAD_STAGE(kt + 2, ld);
            ld = (ld == 2) ? 0 : ld + 1;
        }

        uint32_t soff = (uint32_t)st * STAGE_B;
        st = (st == 2) ? 0 : st + 1;

        #pragma unroll
        for (int ks = 0; ks < 2; ks++) {
            uint32_t bb[2][4];
            #pragma unroll
            for (int p = 0; p < 2; p++)
                ldsm4(bb[p][0], bb[p][1], bb[p][2], bb[p][3],
                      bFrag + soff + (uint32_t)p*16*80 + ks*32);
            #pragma unroll
            for (int mt = 0; mt < 4; mt++) {
                uint32_t aa[4];
                ldsm4(aa[0], aa[1], aa[2], aa[3],
                      aFrag + soff + (uint32_t)mt*16*80 + ks*32);
                mma_f16(acc[mt][0], aa, bb[0][0], bb[0][1]);
                mma_f16(acc[mt][1], aa, bb[0][2], bb[0][3]);
                mma_f16(acc[mt][2], aa, bb[1][0], bb[1][1]);
                mma_f16(acc[mt][3], aa, bb[1][2], bb[1][3]);
            }
        }
    }
    #undef LOAD_STAGE

    // epilogue (col-guarded for N < 128 tiles)
    #pragma unroll
    for (int mt = 0; mt < 4; mt++) {
        #pragma unroll
        for (int nt = 0; nt < 4; nt++) {
            int row0 = m0 + wm*64 + mt*16 + gid;
            int col0 = n0 + wn*32 + nt*8 + tig*2;
            if (col0 >= N) continue;
            #pragma unroll
            for (int half = 0; half < 2; half++) {
                int row = row0 + half*8;
                size_t idx = (size_t)row * N + col0;
                float v0 = acc[mt][nt][half*2 + 0];
                float v1 = acc[mt][nt][half*2 + 1];
                if (mode == 1) {
                    float2 r2 = *(const float2*)(res + idx);
                    float2 e2 = *(const float2*)(extra + idx);
                    v0 = r2.x + v0 + dvec[col0]   * e2.x;
                    v1 = r2.y + v1 + dvec[col0+1] * e2.y;
                    *(float2*)(outf + idx) = make_float2(v0, v1);
                } else if (mode == 2) {
                    float2 g2 = __half22float2(*(const __half2*)(resh + idx));
                    v0 = v0 * (g2.x / (1.f + __expf(-g2.x)));
                    v1 = v1 * (g2.y / (1.f + __expf(-g2.y)));
                    *(__half2*)(outh + idx) = __floats2half2_rn(v0, v1);
                } else if (mode == 3) {
                    float2 r2 = *(const float2*)(res + idx);
                    *(float2*)(outf + idx) = make_float2(v0 + r2.x, v1 + r2.y);
                } else if (mode == 4) {
                    *(__half2*)(outh + idx) = __floats2half2_rn(v0, v1);
                } else {
                    *(float2*)(outf + idx) = make_float2(v0, v1);
                }
            }
        }
    }
}

// ---------------- launch ----------------
extern "C" void kernel_launch(void* const* d_in, const int* in_sizes, int n_in,
                              void* d_out, int out_size)
{
    const float* x      = (const float*)d_in[0];
    const float* A      = (const float*)d_in[1];
    const float* B      = (const float*)d_in[2];
    const float* C      = (const float*)d_in[3];
    const float* D      = (const float*)d_in[4];
    const float* log_dt = (const float*)d_in[5];
    const float* w_gate = (const float*)d_in[6];
    const float* w_up   = (const float*)d_in[7];
    const float* w_down = (const float*)d_in[8];
    const float* ln1    = (const float*)d_in[9];
    const float* ln2    = (const float*)d_in[10];
    float* out = (float*)d_out;

    float *hn1, *h, *U;
    __half *hn1h, *hn2h, *gateh, *acth, *Bbarh, *Ch, *Sh, *wgh, *wuh, *wdh;
    cudaGetSymbolAddress((void**)&hn1,   g_hn1);
    cudaGetSymbolAddress((void**)&hn1h,  g_hn1h);
    cudaGetSymbolAddress((void**)&h,     g_h);
    cudaGetSymbolAddress((void**)&hn2h,  g_hn2h);
    cudaGetSymbolAddress((void**)&U,     g_U);
    cudaGetSymbolAddress((void**)&gateh, g_gateh);
    cudaGetSymbolAddress((void**)&acth,  g_acth);
    cudaGetSymbolAddress((void**)&Bbarh, g_Bbarh);
    cudaGetSymbolAddress((void**)&Ch,    g_Ch);
    cudaGetSymbolAddress((void**)&Sh,    g_Sh);
    cudaGetSymbolAddress((void**)&wgh,   g_wgh);
    cudaGetSymbolAddress((void**)&wuh,   g_wuh);
    cudaGetSymbolAddress((void**)&wdh,   g_wdh);

    cudaFuncSetAttribute(gemm_f16, cudaFuncAttributeMaxDynamicSharedMemorySize, TCSMEM);

    // conversions (independent of SSM path)
    f2h_weights_kernel<<<1024, 256>>>(w_gate, w_up, w_down);
    f2h_kernel<<<64, 256>>>(C, Ch, HIDDEN*STATE/2);

    // SSM path
    prep_kernel<<<1, 512>>>(A, B, log_dt);
    rmsnorm_kernel<<<ROWS, 256>>>(x, ln1, hn1, hn1h);
    // U = hn1 @ Bbar^T  (M=8192, N=64, K=1024)
    gemm_f16<<<dim3(1, ROWS/128), 256, TCSMEM>>>(hn1h, Bbarh, ROWS, STATE, HIDDEN,
                                                 U, nullptr, 0, nullptr, nullptr, nullptr, nullptr);
    local_scan_kernel<<<dim3(NCHUNK, BATCH), 256>>>();
    carry_kernel<<<BATCH, 256>>>();
    fixup_kernel<<<dim3(NCHUNK, BATCH), 256>>>();
    // h = x + S @ C^T + D*hn1  (M=8192, N=1024, K=64)
    gemm_f16<<<dim3(HIDDEN/128, ROWS/128), 256, TCSMEM>>>(Sh, Ch, ROWS, HIDDEN, STATE,
                                                          h, nullptr, 1, x, nullptr, hn1, D);
    // FFN
    rmsnorm_kernel<<<ROWS, 256>>>(h, ln2, nullptr, hn2h);
    gemm_f16<<<dim3(INTER/128, ROWS/128), 256, TCSMEM>>>(hn2h, wgh, ROWS, INTER, HIDDEN,
                                                         nullptr, gateh, 4, nullptr, nullptr, nullptr, nullptr);
    gemm_f16<<<dim3(INTER/128, ROWS/128), 256, TCSMEM>>>(hn2h, wuh, ROWS, INTER, HIDDEN,
                                                         nullptr, acth, 2, nullptr, gateh, nullptr, nullptr);
    gemm_f16<<<dim3(HIDDEN/128, ROWS/128), 256, TCSMEM>>>(acth, wdh, ROWS, HIDDEN, INTER,
                                                          out, nullptr, 3, h, nullptr, nullptr, nullptr);
}

// round 14
// speedup vs baseline: 1.4500x; 1.0143x over previous
#include <cuda_runtime.h>
#include <cuda_fp16.h>
#include <math.h>
#include <stdint.h>

#define HIDDEN 1024
#define STATE  64
#define INTER  4096
#define BATCH  4
#define SEQ    2048
#define ROWS   (BATCH*SEQ)   // 8192
#define NCHUNK 32
#define CLEN   64            // NCHUNK*CLEN == SEQ

// ---------------- scratch (static device allocations; no cudaMalloc) ----------------
__device__ __half g_hn1h[ROWS*HIDDEN];
__device__ float  g_h  [ROWS*HIDDEN];
__device__ __half g_hn2h[ROWS*HIDDEN];
__device__ float  g_U  [ROWS*STATE];
__device__ float  g_S  [ROWS*STATE];
__device__ __half g_Sh [ROWS*STATE];
__device__ __half g_gateh[ROWS*INTER];    // gate pre-activation (half)
__device__ __half g_acth[ROWS*INTER];     // silu(gate)*up (half)
__device__ __half g_Bbarh[128*HIDDEN];    // rows 64..127 stay zero (zero-init)
__device__ __half g_Ch[HIDDEN*STATE];
__device__ float  g_AbT [STATE*STATE];    // AbT[j*64+i] = A_bar[i][j]
__device__ float  g_A64T[STATE*STATE];
__device__ float  g_tail [BATCH*NCHUNK*STATE];
__device__ float  g_carry[BATCH*NCHUNK*STATE];
__device__ __half g_wgh[INTER*HIDDEN];    // fp16 weights
__device__ __half g_wuh[INTER*HIDDEN];
__device__ __half g_wdh[HIDDEN*INTER];

// ================= small-matrix helper: 2 rows x 4 cols per thread =================
__device__ __forceinline__ void mm64_24(const float* __restrict__ X,
                                        const float* __restrict__ Y,
                                        int i0, int j0, float v[8])
{
    #pragma unroll
    for (int c = 0; c < 8; c++) v[c] = 0.f;
    #pragma unroll
    for (int lb = 0; lb < 64; lb += 4) {
        float4 x0 = *(const float4*)&X[(i0+0)*64 + lb];
        float4 x1 = *(const float4*)&X[(i0+1)*64 + lb];
        float4 y0 = *(const float4*)&Y[(lb+0)*64 + j0];
        float4 y1 = *(const float4*)&Y[(lb+1)*64 + j0];
        float4 y2 = *(const float4*)&Y[(lb+2)*64 + j0];
        float4 y3 = *(const float4*)&Y[(lb+3)*64 + j0];
        v[0] += x0.x*y0.x + x0.y*y1.x + x0.z*y2.x + x0.w*y3.x;
        v[1] += x0.x*y0.y + x0.y*y1.y + x0.z*y2.y + x0.w*y3.y;
        v[2] += x0.x*y0.z + x0.y*y1.z + x0.z*y2.z + x0.w*y3.z;
        v[3] += x0.x*y0.w + x0.y*y1.w + x0.z*y2.w + x0.w*y3.w;
        v[4] += x1.x*y0.x + x1.y*y1.x + x1.z*y2.x + x1.w*y3.x;
        v[5] += x1.x*y0.y + x1.y*y1.y + x1.z*y2.y + x1.w*y3.y;
        v[6] += x1.x*y0.z + x1.y*y1.z + x1.z*y2.z + x1.w*y3.z;
        v[7] += x1.x*y0.w + x1.y*y1.w + x1.z*y2.w + x1.w*y3.w;
    }
}

// ---------------- prep (fused, 512 threads): dt, Bbar, expm, A^64 ----------------
__global__ void __launch_bounds__(512) prep_kernel(
    const float* __restrict__ A,
    const float* __restrict__ B,
    const float* __restrict__ log_dt)
{
    __shared__ __align__(16) float Mm[4096];
    __shared__ __align__(16) float Tb[4096];
    __shared__ __align__(16) float Rb[4096];
    int tid = threadIdx.x;                 // 512

    float local = 0.f;
    for (int e = tid; e < HIDDEN; e += 512) {
        float d = expf(log_dt[e]);
        Tb[e] = d;
        local += d;
    }
    Rb[tid] = local;
    __syncthreads();
    for (int s = 256; s > 0; s >>= 1) {
        if (tid < s) Rb[tid] += Rb[tid + s];
        __syncthreads();
    }
    float md = Rb[0] * (1.f / HIDDEN);

    for (int e = tid; e < STATE*HIDDEN; e += 512)
        g_Bbarh[e] = __float2half(B[e] * Tb[e & (HIDDEN - 1)]);
    __syncthreads();

    int i0 = (tid >> 4) * 2;
    int j0 = (tid & 15) * 4;

    for (int e = tid; e < 4096; e += 512) {
        float m = A[e] * md;
        Mm[e] = m; Tb[e] = m;
        Rb[e] = m + ((e >> 6) == (e & 63) ? 1.f : 0.f);
    }
    __syncthreads();

    for (int k = 2; k <= 5; k++) {
        float v[8];
        mm64_24(Tb, Mm, i0, j0, v);
        float inv = 1.f / (float)k;
        __syncthreads();
        #pragma unroll
        for (int r = 0; r < 2; r++)
            #pragma unroll
            for (int c = 0; c < 4; c++) {
                float nv = v[r*4 + c] * inv;
                Tb[(i0+r)*64 + j0 + c] = nv;
                Rb[(i0+r)*64 + j0 + c] += nv;
            }
        __syncthreads();
    }

    #pragma unroll
    for (int r = 0; r < 2; r++)
        #pragma unroll
        for (int c = 0; c < 4; c++)
            g_AbT[(j0+c)*64 + (i0+r)] = Rb[(i0+r)*64 + j0 + c];

    for (int s = 0; s < 6; s++) {
        float v[8];
        mm64_24(Rb, Rb, i0, j0, v);
        __syncthreads();
        #pragma unroll
        for (int r = 0; r < 2; r++)
            #pragma unroll
            for (int c = 0; c < 4; c++)
                Rb[(i0+r)*64 + j0 + c] = v[r*4 + c];
        __syncthreads();
    }
    #pragma unroll
    for (int r = 0; r < 2; r++)
        #pragma unroll
        for (int c = 0; c < 4; c++)
            g_A64T[(j0+c)*64 + (i0+r)] = Rb[(i0+r)*64 + j0 + c];
}

// ---------------- rmsnorm, warp-per-row -> fp16 ----------------
// 1024 CTAs x 256 threads; warp w handles row blockIdx.x*8 + w; shuffle-only reduce.
__global__ void __launch_bounds__(256) rmsnorm_w_kernel(
    const float* __restrict__ x, const float* __restrict__ w,
    __half* __restrict__ outh)
{
    int warp = threadIdx.x >> 5, lane = threadIdx.x & 31;
    int row = blockIdx.x * 8 + warp;
    const float4* xr = (const float4*)(x + (size_t)row * HIDDEN);
    const float4* wr = (const float4*)w;

    float4 v[8];
    float ss = 0.f;
    #pragma unroll
    for (int i = 0; i < 8; i++) {
        v[i] = xr[lane + i*32];
        ss += v[i].x*v[i].x + v[i].y*v[i].y + v[i].z*v[i].z + v[i].w*v[i].w;
    }
    #pragma unroll
    for (int o = 16; o > 0; o >>= 1) ss += __shfl_xor_sync(0xffffffffu, ss, o);
    float s = rsqrtf(ss * (1.f / HIDDEN) + 1e-6f);

    #pragma unroll
    for (int i = 0; i < 8; i++) {
        int j = lane + i*32;
        float4 wv = wr[j];
        union { __half2 h[2]; uint2 u; } pk;
        pk.h[0] = __floats2half2_rn(v[i].x*s*wv.x, v[i].y*s*wv.y);
        pk.h[1] = __floats2half2_rn(v[i].z*s*wv.z, v[i].w*s*wv.w);
        *(uint2*)(outh + (size_t)row * HIDDEN + 4*j) = pk.u;
    }
}

// ---------------- fp32 -> fp16: all FFN weights + C in one launch ----------------
__global__ void f2h_weights_kernel(const float* __restrict__ wg,
                                   const float* __restrict__ wu,
                                   const float* __restrict__ wd,
                                   const float* __restrict__ C)
{
    int i = blockIdx.x * 256 + threadIdx.x;
    int stride = gridDim.x * 256;
    const int n2 = INTER*HIDDEN/2;
    const float2* g2 = (const float2*)wg;
    const float2* u2 = (const float2*)wu;
    const float2* d2 = (const float2*)wd;
    __half2* go = (__half2*)g_wgh;
    __half2* uo = (__half2*)g_wuh;
    __half2* dd = (__half2*)g_wdh;
    for (int k = i; k < n2; k += stride) {
        float2 a = g2[k]; go[k] = __floats2half2_rn(a.x, a.y);
        float2 b = u2[k]; uo[k] = __floats2half2_rn(b.x, b.y);
        float2 c = d2[k]; dd[k] = __floats2half2_rn(c.x, c.y);
    }
    const int n2c = HIDDEN*STATE/2;
    const float2* c2 = (const float2*)C;
    __half2* co = (__half2*)g_Ch;
    for (int k = i; k < n2c; k += stride) {
        float2 c = c2[k]; co[k] = __floats2half2_rn(c.x, c.y);
    }
}

// ---------------- chunked scan ----------------
__global__ void local_scan_kernel()
{
    int c = blockIdx.x, b = blockIdx.y;
    const float* u = g_U + (size_t)(b*SEQ + c*CLEN) * STATE;
    float* sout    = g_S + (size_t)(b*SEQ + c*CLEN) * STATE;

    __shared__ float st[64];
    __shared__ float part[4][64];
    __shared__ float ub[CLEN*64];

    int tid = threadIdx.x;
    int i = tid & 63, p = tid >> 6;

    float a[16];
    #pragma unroll
    for (int jj = 0; jj < 16; jj++) a[jj] = g_AbT[(p*16 + jj)*64 + i];

    for (int e = tid; e < CLEN*64; e += 256) ub[e] = u[e];
    if (tid < 64) st[i] = 0.f;
    __syncthreads();

    for (int t = 0; t < CLEN; t++) {
        float acc = 0.f;
        #pragma unroll
        for (int jj = 0; jj < 16; jj++) acc += a[jj] * st[p*16 + jj];
        part[p][i] = acc;
        __syncthreads();
        if (tid < 64) {
            float v = part[0][i] + part[1][i] + part[2][i] + part[3][i] + ub[t*64 + i];
            st[i] = v;
            sout[(size_t)t*STATE + i] = v;
        }
        __syncthreads();
    }
    if (tid < 64) g_tail[(size_t)(b*NCHUNK + c)*STATE + i] = st[i];
}

__global__ void carry_kernel()
{
    int b = blockIdx.x;
    __shared__ float st[64];
    __shared__ float part[4][64];
    __shared__ float tails[NCHUNK*64];

    int tid = threadIdx.x;
    int i = tid & 63, p = tid >> 6;

    float a[16];
    #pragma unroll
    for (int jj = 0; jj < 16; jj++) a[jj] = g_A64T[(p*16 + jj)*64 + i];

    for (int e = tid; e < NCHUNK*64; e += 256)
        tails[e] = g_tail[(size_t)b*NCHUNK*STATE + e];
    if (tid < 64) {
        st[i] = 0.f;
        g_carry[(size_t)b*NCHUNK*STATE + i] = 0.f;
    }
    __syncthreads();

    for (int c = 1; c < NCHUNK; c++) {
        float acc = 0.f;
        #pragma unroll
        for (int jj = 0; jj < 16; jj++) acc += a[jj] * st[p*16 + jj];
        part[p][i] = acc;
        __syncthreads();
        if (tid < 64) {
            float v = part[0][i] + part[1][i] + part[2][i] + part[3][i]
                    + tails[(c-1)*64 + i];
            st[i] = v;
            g_carry[(size_t)(b*NCHUNK + c)*STATE + i] = v;
        }
        __syncthreads();
    }
}

// fixup: S_final = S_local + A^{t+1} carry; writes HALF S for the tensor GEMM
__global__ void fixup_kernel()
{
    int c = blockIdx.x, b = blockIdx.y;
    const float* sin = g_S  + (size_t)(b*SEQ + c*CLEN) * STATE;
    __half* sout     = g_Sh + (size_t)(b*SEQ + c*CLEN) * STATE;

    __shared__ float st[64];
    __shared__ float part[4][64];

    int tid = threadIdx.x;
    int i = tid & 63, p = tid >> 6;

    float a[16];
    #pragma unroll
    for (int jj = 0; jj < 16; jj++) a[jj] = g_AbT[(p*16 + jj)*64 + i];

    if (tid < 64) st[i] = g_carry[(size_t)(b*NCHUNK + c)*STATE + i];
    __syncthreads();

    for (int t = 0; t < CLEN; t++) {
        float acc = 0.f;
        #pragma unroll
        for (int jj = 0; jj < 16; jj++) acc += a[jj] * st[p*16 + jj];
        part[p][i] = acc;
        __syncthreads();
        if (tid < 64) {
            float v = part[0][i] + part[1][i] + part[2][i] + part[3][i];
            st[i] = v;
            sout[(size_t)t*STATE + i] = __float2half(v + sin[(size_t)t*STATE + i]);
        }
        __syncthreads();
    }
}

// ================= fp16 tensor-core GEMM (R7 v3): C = A[M,K] @ B[N,K]^T =================
__device__ __forceinline__ void ldsm4(uint32_t& r0, uint32_t& r1,
                                      uint32_t& r2, uint32_t& r3, uint32_t addr)
{
    asm volatile("ldmatrix.sync.aligned.m8n8.x4.shared.b16 {%0,%1,%2,%3}, [%4];"
                 : "=r"(r0), "=r"(r1), "=r"(r2), "=r"(r3) : "r"(addr));
}
__device__ __forceinline__ void cp16s(uint32_t saddr, const void* g)
{
    asm volatile("cp.async.cg.shared.global [%0], [%1], 16;" :: "r"(saddr), "l"(g));
}
__device__ __forceinline__ void mma_f16(float* d, const uint32_t a[4],
                                        uint32_t b0, uint32_t b1)
{
    asm volatile(
        "mma.sync.aligned.m16n8k16.row.col.f32.f16.f16.f32 "
        "{%0,%1,%2,%3}, {%4,%5,%6,%7}, {%8,%9}, {%0,%1,%2,%3};\n"
        : "+f"(d[0]), "+f"(d[1]), "+f"(d[2]), "+f"(d[3])
        : "r"(a[0]), "r"(a[1]), "r"(a[2]), "r"(a[3]), "r"(b0), "r"(b1));
}

#define STAGE_B 20480        // bytes per stage (A 10240 + B 10240), row pitch 80B
#define TCSMEM  (3*STAGE_B)  // 61440

// modes: 0 outf=acc; 1 outf = res + acc + dvec[col]*extrah(half);
//        2 outh = half(silu(resh)*acc); 3 outf = res + acc; 4 outh = half(acc)
__global__ void __launch_bounds__(256) gemm_f16(
    const __half* __restrict__ A, const __half* __restrict__ Bm,
    int M, int N, int K, float* __restrict__ outf, __half* __restrict__ outh,
    int mode, const float* __restrict__ res, const __half* __restrict__ resh,
    const __half* __restrict__ extrah, const float* __restrict__ dvec)
{
    extern __shared__ __align__(16) char smem[];
    uint32_t smBase = (uint32_t)__cvta_generic_to_shared(smem);
    int tid = threadIdx.x;
    int m0 = blockIdx.y * 128, n0 = blockIdx.x * 128;

    int lr = tid >> 1, lc = (tid & 1) * 2;
    const __half* Ag = A  + (size_t)(m0 + lr) * K + lc*8;
    const __half* Bg = Bm + (size_t)(n0 + lr) * K + lc*8;
    uint32_t aDst = smBase + lr*80 + lc*16;
    uint32_t bDst = smBase + 10240 + lr*80 + lc*16;

    int lane = tid & 31, warp = tid >> 5;
    int wm = warp & 1, wn = warp >> 1;
    int gid = lane >> 2, tig = lane & 3;

    uint32_t aFrag = smBase
        + (uint32_t)(wm*64 + (lane & 7) + ((lane >> 3) & 1)*8) * 80
        + ((lane >> 4) & 1) * 16;
    uint32_t bFrag = smBase + 10240
        + (uint32_t)(wn*32 + ((lane >> 4) & 1)*8 + (lane & 7)) * 80
        + ((lane >> 3) & 1) * 16;

    float acc[4][4][4];
    #pragma unroll
    for (int mt = 0; mt < 4; mt++)
        #pragma unroll
        for (int nt = 0; nt < 4; nt++)
            #pragma unroll
            for (int r = 0; r < 4; r++) acc[mt][nt][r] = 0.f;

    int NT = K >> 5;

    #define LOAD_STAGE(kt, s) do {                                           \
        uint32_t off_ = (uint32_t)(s) * STAGE_B;                             \
        const __half* ga_ = Ag + (size_t)(kt)*32;                            \
        const __half* gb_ = Bg + (size_t)(kt)*32;                            \
        cp16s(aDst + off_,      ga_);                                        \
        cp16s(aDst + off_ + 16, ga_ + 8);                                    \
        cp16s(bDst + off_,      gb_);                                        \
        cp16s(bDst + off_ + 16, gb_ + 8);                                    \
        asm volatile("cp.async.commit_group;\n");                            \
    } while (0)

    LOAD_STAGE(0, 0);
    if (NT > 1) LOAD_STAGE(1, 1);

    int st = 0, ld = 2;
    for (int kt = 0; kt < NT; kt++) {
        if (kt + 1 < NT) asm volatile("cp.async.wait_group 1;\n");
        else             asm volatile("cp.async.wait_group 0;\n");
        __syncthreads();

        if (kt + 2 < NT) {
            LOAD_STAGE(kt + 2, ld);
            ld = (ld == 2) ? 0 : ld + 1;
        }

        uint32_t soff = (uint32_t)st * STAGE_B;
        st = (st == 2) ? 0 : st + 1;

        #pragma unroll
        for (int ks = 0; ks < 2; ks++) {
            uint32_t bb[2][4];
            #pragma unroll
            for (int p = 0; p < 2; p++)
                ldsm4(bb[p][0], bb[p][1], bb[p][2], bb[p][3],
                      bFrag + soff + (uint32_t)p*16*80 + ks*32);
            #pragma unroll
            for (int mt = 0; mt < 4; mt++) {
                uint32_t aa[4];
                ldsm4(aa[0], aa[1], aa[2], aa[3],
                      aFrag + soff + (uint32_t)mt*16*80 + ks*32);
                mma_f16(acc[mt][0], aa, bb[0][0], bb[0][1]);
                mma_f16(acc[mt][1], aa, bb[0][2], bb[0][3]);
                mma_f16(acc[mt][2], aa, bb[1][0], bb[1][1]);
                mma_f16(acc[mt][3], aa, bb[1][2], bb[1][3]);
            }
        }
    }
    #undef LOAD_STAGE

    // epilogue (col-guarded for N < 128 tiles)
    #pragma unroll
    for (int mt = 0; mt < 4; mt++) {
        #pragma unroll
        for (int nt = 0; nt < 4; nt++) {
            int row0 = m0 + wm*64 + mt*16 + gid;
            int col0 = n0 + wn*32 + nt*8 + tig*2;
            if (col0 >= N) continue;
            #pragma unroll
            for (int half = 0; half < 2; half++) {
                int row = row0 + half*8;
                size_t idx = (size_t)row * N + col0;
                float v0 = acc[mt][nt][half*2 + 0];
                float v1 = acc[mt][nt][half*2 + 1];
                if (mode == 1) {
                    float2 r2 = *(const float2*)(res + idx);
                    float2 e2 = __half22float2(*(const __half2*)(extrah + idx));
                    v0 = r2.x + v0 + dvec[col0]   * e2.x;
                    v1 = r2.y + v1 + dvec[col0+1] * e2.y;
                    *(float2*)(outf + idx) = make_float2(v0, v1);
                } else if (mode == 2) {
                    float2 g2 = __half22float2(*(const __half2*)(resh + idx));
                    v0 = v0 * (g2.x / (1.f + __expf(-g2.x)));
                    v1 = v1 * (g2.y / (1.f + __expf(-g2.y)));
                    *(__half2*)(outh + idx) = __floats2half2_rn(v0, v1);
                } else if (mode == 3) {
                    float2 r2 = *(const float2*)(res + idx);
                    *(float2*)(outf + idx) = make_float2(v0 + r2.x, v1 + r2.y);
                } else if (mode == 4) {
                    *(__half2*)(outh + idx) = __floats2half2_rn(v0, v1);
                } else {
                    *(float2*)(outf + idx) = make_float2(v0, v1);
                }
            }
        }
    }
}

// ---------------- launch ----------------
extern "C" void kernel_launch(void* const* d_in, const int* in_sizes, int n_in,
                              void* d_out, int out_size)
{
    const float* x      = (const float*)d_in[0];
    const float* A      = (const float*)d_in[1];
    const float* B      = (const float*)d_in[2];
    const float* C      = (const float*)d_in[3];
    const float* D      = (const float*)d_in[4];
    const float* log_dt = (const float*)d_in[5];
    const float* w_gate = (const float*)d_in[6];
    const float* w_up   = (const float*)d_in[7];
    const float* w_down = (const float*)d_in[8];
    const float* ln1    = (const float*)d_in[9];
    const float* ln2    = (const float*)d_in[10];
    float* out = (float*)d_out;

    float *h, *U;
    __half *hn1h, *hn2h, *gateh, *acth, *Bbarh, *Ch, *Sh, *wgh, *wuh, *wdh;
    cudaGetSymbolAddress((void**)&hn1h,  g_hn1h);
    cudaGetSymbolAddress((void**)&h,     g_h);
    cudaGetSymbolAddress((void**)&hn2h,  g_hn2h);
    cudaGetSymbolAddress((void**)&U,     g_U);
    cudaGetSymbolAddress((void**)&gateh, g_gateh);
    cudaGetSymbolAddress((void**)&acth,  g_acth);
    cudaGetSymbolAddress((void**)&Bbarh, g_Bbarh);
    cudaGetSymbolAddress((void**)&Ch,    g_Ch);
    cudaGetSymbolAddress((void**)&Sh,    g_Sh);
    cudaGetSymbolAddress((void**)&wgh,   g_wgh);
    cudaGetSymbolAddress((void**)&wuh,   g_wuh);
    cudaGetSymbolAddress((void**)&wdh,   g_wdh);

    cudaFuncSetAttribute(gemm_f16, cudaFuncAttributeMaxDynamicSharedMemorySize, TCSMEM);

    // conversions (weights + C, one launch)
    f2h_weights_kernel<<<1024, 256>>>(w_gate, w_up, w_down, C);

    // SSM path
    prep_kernel<<<1, 512>>>(A, B, log_dt);
    rmsnorm_w_kernel<<<ROWS/8, 256>>>(x, ln1, hn1h);
    // U = hn1 @ Bbar^T  (M=8192, N=64, K=1024)
    gemm_f16<<<dim3(1, ROWS/128), 256, TCSMEM>>>(hn1h, Bbarh, ROWS, STATE, HIDDEN,
                                                 U, nullptr, 0, nullptr, nullptr, nullptr, nullptr);
    local_scan_kernel<<<dim3(NCHUNK, BATCH), 256>>>();
    carry_kernel<<<BATCH, 256>>>();
    fixup_kernel<<<dim3(NCHUNK, BATCH), 256>>>();
    // h = x + S @ C^T + D*hn1  (M=8192, N=1024, K=64)
    gemm_f16<<<dim3(HIDDEN/128, ROWS/128), 256, TCSMEM>>>(Sh, Ch, ROWS, HIDDEN, STATE,
                                                          h, nullptr, 1, x, nullptr, hn1h, D);
    // FFN
    rmsnorm_w_kernel<<<ROWS/8, 256>>>(h, ln2, hn2h);
    gemm_f16<<<dim3(INTER/128, ROWS/128), 256, TCSMEM>>>(hn2h, wgh, ROWS, INTER, HIDDEN,
                                                         nullptr, gateh, 4, nullptr, nullptr, nullptr, nullptr);
    gemm_f16<<<dim3(INTER/128, ROWS/128), 256, TCSMEM>>>(hn2h, wuh, ROWS, INTER, HIDDEN,
                                                         nullptr, acth, 2, nullptr, gateh, nullptr, nullptr);
    gemm_f16<<<dim3(HIDDEN/128, ROWS/128), 256, TCSMEM>>>(acth, wdh, ROWS, HIDDEN, INTER,
                                                          out, nullptr, 3, h, nullptr, nullptr, nullptr);
}

// round 15
// speedup vs baseline: 1.4721x; 1.0152x over previous
#include <cuda_runtime.h>
#include <cuda_fp16.h>
#include <math.h>
#include <stdint.h>

#define HIDDEN 1024
#define STATE  64
#define INTER  4096
#define BATCH  4
#define SEQ    2048
#define ROWS   (BATCH*SEQ)   // 8192
#define NCHUNK 32
#define CLEN   64            // NCHUNK*CLEN == SEQ
#define KSPLIT 4             // split-K for the U GEMM

// ---------------- scratch (static device allocations; no cudaMalloc) ----------------
__device__ __half g_hn1h[ROWS*HIDDEN];
__device__ float  g_h  [ROWS*HIDDEN];
__device__ __half g_hn2h[ROWS*HIDDEN];
__device__ float  g_U  [KSPLIT*ROWS*STATE];   // split-K partials
__device__ float  g_S  [ROWS*STATE];
__device__ __half g_Sh [ROWS*STATE];
__device__ __half g_gateh[ROWS*INTER];    // gate pre-activation (half)
__device__ __half g_acth[ROWS*INTER];     // silu(gate)*up (half)
__device__ __half g_Bbarh[128*HIDDEN];    // rows 64..127 stay zero (zero-init)
__device__ __half g_Ch[HIDDEN*STATE];
__device__ float  g_AbT [STATE*STATE];    // AbT[j*64+i] = A_bar[i][j]
__device__ float  g_A64T[STATE*STATE];
__device__ float  g_tail [BATCH*NCHUNK*STATE];
__device__ float  g_carry[BATCH*NCHUNK*STATE];
__device__ __half g_wgh[INTER*HIDDEN];    // fp16 weights
__device__ __half g_wuh[INTER*HIDDEN];
__device__ __half g_wdh[HIDDEN*INTER];

// ================= small-matrix helper: 2 rows x 4 cols per thread =================
__device__ __forceinline__ void mm64_24(const float* __restrict__ X,
                                        const float* __restrict__ Y,
                                        int i0, int j0, float v[8])
{
    #pragma unroll
    for (int c = 0; c < 8; c++) v[c] = 0.f;
    #pragma unroll
    for (int lb = 0; lb < 64; lb += 4) {
        float4 x0 = *(const float4*)&X[(i0+0)*64 + lb];
        float4 x1 = *(const float4*)&X[(i0+1)*64 + lb];
        float4 y0 = *(const float4*)&Y[(lb+0)*64 + j0];
        float4 y1 = *(const float4*)&Y[(lb+1)*64 + j0];
        float4 y2 = *(const float4*)&Y[(lb+2)*64 + j0];
        float4 y3 = *(const float4*)&Y[(lb+3)*64 + j0];
        v[0] += x0.x*y0.x + x0.y*y1.x + x0.z*y2.x + x0.w*y3.x;
        v[1] += x0.x*y0.y + x0.y*y1.y + x0.z*y2.y + x0.w*y3.y;
        v[2] += x0.x*y0.z + x0.y*y1.z + x0.z*y2.z + x0.w*y3.z;
        v[3] += x0.x*y0.w + x0.y*y1.w + x0.z*y2.w + x0.w*y3.w;
        v[4] += x1.x*y0.x + x1.y*y1.x + x1.z*y2.x + x1.w*y3.x;
        v[5] += x1.x*y0.y + x1.y*y1.y + x1.z*y2.y + x1.w*y3.y;
        v[6] += x1.x*y0.z + x1.y*y1.z + x1.z*y2.z + x1.w*y3.z;
        v[7] += x1.x*y0.w + x1.y*y1.w + x1.z*y2.w + x1.w*y3.w;
    }
}

// ---------------- prep (fused, 512 threads): dt, Bbar, expm, A^64 ----------------
__global__ void __launch_bounds__(512) prep_kernel(
    const float* __restrict__ A,
    const float* __restrict__ B,
    const float* __restrict__ log_dt)
{
    __shared__ __align__(16) float Mm[4096];
    __shared__ __align__(16) float Tb[4096];
    __shared__ __align__(16) float Rb[4096];
    int tid = threadIdx.x;                 // 512

    float local = 0.f;
    for (int e = tid; e < HIDDEN; e += 512) {
        float d = expf(log_dt[e]);
        Tb[e] = d;
        local += d;
    }
    Rb[tid] = local;
    __syncthreads();
    for (int s = 256; s > 0; s >>= 1) {
        if (tid < s) Rb[tid] += Rb[tid + s];
        __syncthreads();
    }
    float md = Rb[0] * (1.f / HIDDEN);

    for (int e = tid; e < STATE*HIDDEN; e += 512)
        g_Bbarh[e] = __float2half(B[e] * Tb[e & (HIDDEN - 1)]);
    __syncthreads();

    int i0 = (tid >> 4) * 2;
    int j0 = (tid & 15) * 4;

    for (int e = tid; e < 4096; e += 512) {
        float m = A[e] * md;
        Mm[e] = m; Tb[e] = m;
        Rb[e] = m + ((e >> 6) == (e & 63) ? 1.f : 0.f);
    }
    __syncthreads();

    for (int k = 2; k <= 5; k++) {
        float v[8];
        mm64_24(Tb, Mm, i0, j0, v);
        float inv = 1.f / (float)k;
        __syncthreads();
        #pragma unroll
        for (int r = 0; r < 2; r++)
            #pragma unroll
            for (int c = 0; c < 4; c++) {
                float nv = v[r*4 + c] * inv;
                Tb[(i0+r)*64 + j0 + c] = nv;
                Rb[(i0+r)*64 + j0 + c] += nv;
            }
        __syncthreads();
    }

    #pragma unroll
    for (int r = 0; r < 2; r++)
        #pragma unroll
        for (int c = 0; c < 4; c++)
            g_AbT[(j0+c)*64 + (i0+r)] = Rb[(i0+r)*64 + j0 + c];

    for (int s = 0; s < 6; s++) {
        float v[8];
        mm64_24(Rb, Rb, i0, j0, v);
        __syncthreads();
        #pragma unroll
        for (int r = 0; r < 2; r++)
            #pragma unroll
            for (int c = 0; c < 4; c++)
                Rb[(i0+r)*64 + j0 + c] = v[r*4 + c];
        __syncthreads();
    }
    #pragma unroll
    for (int r = 0; r < 2; r++)
        #pragma unroll
        for (int c = 0; c < 4; c++)
            g_A64T[(j0+c)*64 + (i0+r)] = Rb[(i0+r)*64 + j0 + c];
}

// ---------------- rmsnorm, warp-per-row -> fp16 ----------------
__global__ void __launch_bounds__(256) rmsnorm_w_kernel(
    const float* __restrict__ x, const float* __restrict__ w,
    __half* __restrict__ outh)
{
    int warp = threadIdx.x >> 5, lane = threadIdx.x & 31;
    int row = blockIdx.x * 8 + warp;
    const float4* xr = (const float4*)(x + (size_t)row * HIDDEN);
    const float4* wr = (const float4*)w;

    float4 v[8];
    float ss = 0.f;
    #pragma unroll
    for (int i = 0; i < 8; i++) {
        v[i] = xr[lane + i*32];
        ss += v[i].x*v[i].x + v[i].y*v[i].y + v[i].z*v[i].z + v[i].w*v[i].w;
    }
    #pragma unroll
    for (int o = 16; o > 0; o >>= 1) ss += __shfl_xor_sync(0xffffffffu, ss, o);
    float s = rsqrtf(ss * (1.f / HIDDEN) + 1e-6f);

    #pragma unroll
    for (int i = 0; i < 8; i++) {
        int j = lane + i*32;
        float4 wv = wr[j];
        union { __half2 h[2]; uint2 u; } pk;
        pk.h[0] = __floats2half2_rn(v[i].x*s*wv.x, v[i].y*s*wv.y);
        pk.h[1] = __floats2half2_rn(v[i].z*s*wv.z, v[i].w*s*wv.w);
        *(uint2*)(outh + (size_t)row * HIDDEN + 4*j) = pk.u;
    }
}

// ---------------- fp32 -> fp16: all FFN weights + C in one launch ----------------
__global__ void f2h_weights_kernel(const float* __restrict__ wg,
                                   const float* __restrict__ wu,
                                   const float* __restrict__ wd,
                                   const float* __restrict__ C)
{
    int i = blockIdx.x * 256 + threadIdx.x;
    int stride = gridDim.x * 256;
    const int n2 = INTER*HIDDEN/2;
    const float2* g2 = (const float2*)wg;
    const float2* u2 = (const float2*)wu;
    const float2* d2 = (const float2*)wd;
    __half2* go = (__half2*)g_wgh;
    __half2* uo = (__half2*)g_wuh;
    __half2* dd = (__half2*)g_wdh;
    for (int k = i; k < n2; k += stride) {
        float2 a = g2[k]; go[k] = __floats2half2_rn(a.x, a.y);
        float2 b = u2[k]; uo[k] = __floats2half2_rn(b.x, b.y);
        float2 c = d2[k]; dd[k] = __floats2half2_rn(c.x, c.y);
    }
    const int n2c = HIDDEN*STATE/2;
    const float2* c2 = (const float2*)C;
    __half2* co = (__half2*)g_Ch;
    for (int k = i; k < n2c; k += stride) {
        float2 c = c2[k]; co[k] = __floats2half2_rn(c.x, c.y);
    }
}

// ---------------- chunked scan ----------------
__global__ void local_scan_kernel()
{
    int c = blockIdx.x, b = blockIdx.y;
    size_t ubase = (size_t)(b*SEQ + c*CLEN) * STATE;
    float* sout  = g_S + ubase;

    __shared__ float st[64];
    __shared__ float part[4][64];
    __shared__ float ub[CLEN*64];

    int tid = threadIdx.x;
    int i = tid & 63, p = tid >> 6;

    float a[16];
    #pragma unroll
    for (int jj = 0; jj < 16; jj++) a[jj] = g_AbT[(p*16 + jj)*64 + i];

    for (int e = tid; e < CLEN*64; e += 256) {
        size_t idx = ubase + e;
        ub[e] = g_U[idx] + g_U[(size_t)ROWS*STATE + idx]
              + g_U[2*(size_t)ROWS*STATE + idx] + g_U[3*(size_t)ROWS*STATE + idx];
    }
    if (tid < 64) st[i] = 0.f;
    __syncthreads();

    for (int t = 0; t < CLEN; t++) {
        float acc = 0.f;
        #pragma unroll
        for (int jj = 0; jj < 16; jj++) acc += a[jj] * st[p*16 + jj];
        part[p][i] = acc;
        __syncthreads();
        if (tid < 64) {
            float v = part[0][i] + part[1][i] + part[2][i] + part[3][i] + ub[t*64 + i];
            st[i] = v;
            sout[(size_t)t*STATE + i] = v;
        }
        __syncthreads();
    }
    if (tid < 64) g_tail[(size_t)(b*NCHUNK + c)*STATE + i] = st[i];
}

__global__ void carry_kernel()
{
    int b = blockIdx.x;
    __shared__ float st[64];
    __shared__ float part[4][64];
    __shared__ float tails[NCHUNK*64];

    int tid = threadIdx.x;
    int i = tid & 63, p = tid >> 6;

    float a[16];
    #pragma unroll
    for (int jj = 0; jj < 16; jj++) a[jj] = g_A64T[(p*16 + jj)*64 + i];

    for (int e = tid; e < NCHUNK*64; e += 256)
        tails[e] = g_tail[(size_t)b*NCHUNK*STATE + e];
    if (tid < 64) {
        st[i] = 0.f;
        g_carry[(size_t)b*NCHUNK*STATE + i] = 0.f;
    }
    __syncthreads();

    for (int c = 1; c < NCHUNK; c++) {
        float acc = 0.f;
        #pragma unroll
        for (int jj = 0; jj < 16; jj++) acc += a[jj] * st[p*16 + jj];
        part[p][i] = acc;
        __syncthreads();
        if (tid < 64) {
            float v = part[0][i] + part[1][i] + part[2][i] + part[3][i]
                    + tails[(c-1)*64 + i];
            st[i] = v;
            g_carry[(size_t)(b*NCHUNK + c)*STATE + i] = v;
        }
        __syncthreads();
    }
}

// fixup: S_final = S_local + A^{t+1} carry; writes HALF S for the tensor GEMM
__global__ void fixup_kernel()
{
    int c = blockIdx.x, b = blockIdx.y;
    const float* sin = g_S  + (size_t)(b*SEQ + c*CLEN) * STATE;
    __half* sout     = g_Sh + (size_t)(b*SEQ + c*CLEN) * STATE;

    __shared__ float st[64];
    __shared__ float part[4][64];

    int tid = threadIdx.x;
    int i = tid & 63, p = tid >> 6;

    float a[16];
    #pragma unroll
    for (int jj = 0; jj < 16; jj++) a[jj] = g_AbT[(p*16 + jj)*64 + i];

    if (tid < 64) st[i] = g_carry[(size_t)(b*NCHUNK + c)*STATE + i];
    __syncthreads();

    for (int t = 0; t < CLEN; t++) {
        float acc = 0.f;
        #pragma unroll
        for (int jj = 0; jj < 16; jj++) acc += a[jj] * st[p*16 + jj];
        part[p][i] = acc;
        __syncthreads();
        if (tid < 64) {
            float v = part[0][i] + part[1][i] + part[2][i] + part[3][i];
            st[i] = v;
            sout[(size_t)t*STATE + i] = __float2half(v + sin[(size_t)t*STATE + i]);
        }
        __syncthreads();
    }
}

// ================= fp16 tensor-core GEMM (R7 v3 + split-K): C = A[M,K] @ B[N,K]^T ==========
__device__ __forceinline__ void ldsm4(uint32_t& r0, uint32_t& r1,
                                      uint32_t& r2, uint32_t& r3, uint32_t addr)
{
    asm volatile("ldmatrix.sync.aligned.m8n8.x4.shared.b16 {%0,%1,%2,%3}, [%4];"
                 : "=r"(r0), "=r"(r1), "=r"(r2), "=r"(r3) : "r"(addr));
}
__device__ __forceinline__ void cp16s(uint32_t saddr, const void* g)
{
    asm volatile("cp.async.cg.shared.global [%0], [%1], 16;" :: "r"(saddr), "l"(g));
}
__device__ __forceinline__ void mma_f16(float* d, const uint32_t a[4],
                                        uint32_t b0, uint32_t b1)
{
    asm volatile(
        "mma.sync.aligned.m16n8k16.row.col.f32.f16.f16.f32 "
        "{%0,%1,%2,%3}, {%4,%5,%6,%7}, {%8,%9}, {%0,%1,%2,%3};\n"
        : "+f"(d[0]), "+f"(d[1]), "+f"(d[2]), "+f"(d[3])
        : "r"(a[0]), "r"(a[1]), "r"(a[2]), "r"(a[3]), "r"(b0), "r"(b1));
}

#define STAGE_B 20480        // bytes per stage (A 10240 + B 10240), row pitch 80B
#define TCSMEM  (3*STAGE_B)  // 61440

// K = compute-K per blockIdx.z slice; kld = row stride of A and B in elements.
// blockIdx.z selects K-slice z*K.. and (mode 0) output partial buffer z.
// modes: 0 outf[z*M*N + idx]=acc; 1 outf = res + acc + dvec[col]*extrah(half);
//        2 outh = half(silu(resh)*acc); 3 outf = res + acc; 4 outh = half(acc)
__global__ void __launch_bounds__(256) gemm_f16(
    const __half* __restrict__ A, const __half* __restrict__ Bm,
    int M, int N, int K, int kld, float* __restrict__ outf, __half* __restrict__ outh,
    int mode, const float* __restrict__ res, const __half* __restrict__ resh,
    const __half* __restrict__ extrah, const float* __restrict__ dvec)
{
    extern __shared__ __align__(16) char smem[];
    uint32_t smBase = (uint32_t)__cvta_generic_to_shared(smem);
    int tid = threadIdx.x;
    int m0 = blockIdx.y * 128, n0 = blockIdx.x * 128;
    int koff = blockIdx.z * K;

    int lr = tid >> 1, lc = (tid & 1) * 2;
    const __half* Ag = A  + (size_t)(m0 + lr) * kld + koff + lc*8;
    const __half* Bg = Bm + (size_t)(n0 + lr) * kld + koff + lc*8;
    uint32_t aDst = smBase + lr*80 + lc*16;
    uint32_t bDst = smBase + 10240 + lr*80 + lc*16;

    int lane = tid & 31, warp = tid >> 5;
    int wm = warp & 1, wn = warp >> 1;
    int gid = lane >> 2, tig = lane & 3;

    uint32_t aFrag = smBase
        + (uint32_t)(wm*64 + (lane & 7) + ((lane >> 3) & 1)*8) * 80
        + ((lane >> 4) & 1) * 16;
    uint32_t bFrag = smBase + 10240
        + (uint32_t)(wn*32 + ((lane >> 4) & 1)*8 + (lane & 7)) * 80
        + ((lane >> 3) & 1) * 16;

    float acc[4][4][4];
    #pragma unroll
    for (int mt = 0; mt < 4; mt++)
        #pragma unroll
        for (int nt = 0; nt < 4; nt++)
            #pragma unroll
            for (int r = 0; r < 4; r++) acc[mt][nt][r] = 0.f;

    int NT = K >> 5;

    #define LOAD_STAGE(kt, s) do {                                           \
        uint32_t off_ = (uint32_t)(s) * STAGE_B;                             \
        const __half* ga_ = Ag + (size_t)(kt)*32;                            \
        const __half* gb_ = Bg + (size_t)(kt)*32;                            \
        cp16s(aDst + off_,      ga_);                                        \
        cp16s(aDst + off_ + 16, ga_ + 8);                                    \
        cp16s(bDst + off_,      gb_);                                        \
        cp16s(bDst + off_ + 16, gb_ + 8);                                    \
        asm volatile("cp.async.commit_group;\n");                            \
    } while (0)

    LOAD_STAGE(0, 0);
    if (NT > 1) LOAD_STAGE(1, 1);

    int st = 0, ld = 2;
    for (int kt = 0; kt < NT; kt++) {
        if (kt + 1 < NT) asm volatile("cp.async.wait_group 1;\n");
        else             asm volatile("cp.async.wait_group 0;\n");
        __syncthreads();

        if (kt + 2 < NT) {
            LOAD_STAGE(kt + 2, ld);
            ld = (ld == 2) ? 0 : ld + 1;
        }

        uint32_t soff = (uint32_t)st * STAGE_B;
        st = (st == 2) ? 0 : st + 1;

        #pragma unroll
        for (int ks = 0; ks < 2; ks++) {
            uint32_t bb[2][4];
            #pragma unroll
            for (int p = 0; p < 2; p++)
                ldsm4(bb[p][0], bb[p][1], bb[p][2], bb[p][3],
                      bFrag + soff + (uint32_t)p*16*80 + ks*32);
            #pragma unroll
            for (int mt = 0; mt < 4; mt++) {
                uint32_t aa[4];
                ldsm4(aa[0], aa[1], aa[2], aa[3],
                      aFrag + soff + (uint32_t)mt*16*80 + ks*32);
                mma_f16(acc[mt][0], aa, bb[0][0], bb[0][1]);
                mma_f16(acc[mt][1], aa, bb[0][2], bb[0][3]);
                mma_f16(acc[mt][2], aa, bb[1][0], bb[1][1]);
                mma_f16(acc[mt][3], aa, bb[1][2], bb[1][3]);
            }
        }
    }
    #undef LOAD_STAGE

    float* outz = outf + (mode == 0 ? (size_t)blockIdx.z * M * N : 0);

    // epilogue (col-guarded for N < 128 tiles)
    #pragma unroll
    for (int mt = 0; mt < 4; mt++) {
        #pragma unroll
        for (int nt = 0; nt < 4; nt++) {
            int row0 = m0 + wm*64 + mt*16 + gid;
            int col0 = n0 + wn*32 + nt*8 + tig*2;
            if (col0 >= N) continue;
            #pragma unroll
            for (int half = 0; half < 2; half++) {
                int row = row0 + half*8;
                size_t idx = (size_t)row * N + col0;
                float v0 = acc[mt][nt][half*2 + 0];
                float v1 = acc[mt][nt][half*2 + 1];
                if (mode == 1) {
                    float2 r2 = *(const float2*)(res + idx);
                    float2 e2 = __half22float2(*(const __half2*)(extrah + idx));
                    v0 = r2.x + v0 + dvec[col0]   * e2.x;
                    v1 = r2.y + v1 + dvec[col0+1] * e2.y;
                    *(float2*)(outf + idx) = make_float2(v0, v1);
                } else if (mode == 2) {
                    float2 g2 = __half22float2(*(const __half2*)(resh + idx));
                    v0 = v0 * (g2.x / (1.f + __expf(-g2.x)));
                    v1 = v1 * (g2.y / (1.f + __expf(-g2.y)));
                    *(__half2*)(outh + idx) = __floats2half2_rn(v0, v1);
                } else if (mode == 3) {
                    float2 r2 = *(const float2*)(res + idx);
                    *(float2*)(outf + idx) = make_float2(v0 + r2.x, v1 + r2.y);
                } else if (mode == 4) {
                    *(__half2*)(outh + idx) = __floats2half2_rn(v0, v1);
                } else {
                    *(float2*)(outz + idx) = make_float2(v0, v1);
                }
            }
        }
    }
}

// ---------------- launch ----------------
extern "C" void kernel_launch(void* const* d_in, const int* in_sizes, int n_in,
                              void* d_out, int out_size)
{
    const float* x      = (const float*)d_in[0];
    const float* A      = (const float*)d_in[1];
    const float* B      = (const float*)d_in[2];
    const float* C      = (const float*)d_in[3];
    const float* D      = (const float*)d_in[4];
    const float* log_dt = (const float*)d_in[5];
    const float* w_gate = (const float*)d_in[6];
    const float* w_up   = (const float*)d_in[7];
    const float* w_down = (const float*)d_in[8];
    const float* ln1    = (const float*)d_in[9];
    const float* ln2    = (const float*)d_in[10];
    float* out = (float*)d_out;

    float *h, *U;
    __half *hn1h, *hn2h, *gateh, *acth, *Bbarh, *Ch, *Sh, *wgh, *wuh, *wdh;
    cudaGetSymbolAddress((void**)&hn1h,  g_hn1h);
    cudaGetSymbolAddress((void**)&h,     g_h);
    cudaGetSymbolAddress((void**)&hn2h,  g_hn2h);
    cudaGetSymbolAddress((void**)&U,     g_U);
    cudaGetSymbolAddress((void**)&gateh, g_gateh);
    cudaGetSymbolAddress((void**)&acth,  g_acth);
    cudaGetSymbolAddress((void**)&Bbarh, g_Bbarh);
    cudaGetSymbolAddress((void**)&Ch,    g_Ch);
    cudaGetSymbolAddress((void**)&Sh,    g_Sh);
    cudaGetSymbolAddress((void**)&wgh,   g_wgh);
    cudaGetSymbolAddress((void**)&wuh,   g_wuh);
    cudaGetSymbolAddress((void**)&wdh,   g_wdh);

    cudaFuncSetAttribute(gemm_f16, cudaFuncAttributeMaxDynamicSharedMemorySize, TCSMEM);

    // one-time side stream + events (host objects; no device memory)
    static cudaStream_t s2 = nullptr;
    static cudaEvent_t evF = nullptr, evJ = nullptr;
    if (s2 == nullptr) {
        cudaStreamCreateWithFlags(&s2, cudaStreamNonBlocking);
        cudaEventCreateWithFlags(&evF, cudaEventDisableTiming);
        cudaEventCreateWithFlags(&evJ, cudaEventDisableTiming);
    }

    // fork: weights conversion + rmsnorm1 on s2, prep on main stream
    cudaEventRecord(evF, 0);
    cudaStreamWaitEvent(s2, evF, 0);
    f2h_weights_kernel<<<1024, 256, 0, s2>>>(w_gate, w_up, w_down, C);
    rmsnorm_w_kernel<<<ROWS/8, 256, 0, s2>>>(x, ln1, hn1h);
    cudaEventRecord(evJ, s2);

    prep_kernel<<<1, 512>>>(A, B, log_dt);
    cudaStreamWaitEvent(0, evJ, 0);

    // U partials = hn1 @ Bbar^T  (M=8192, N=64, K=1024 split into 4x256)
    gemm_f16<<<dim3(1, ROWS/128, KSPLIT), 256, TCSMEM>>>(
        hn1h, Bbarh, ROWS, STATE, HIDDEN/KSPLIT, HIDDEN,
        U, nullptr, 0, nullptr, nullptr, nullptr, nullptr);
    local_scan_kernel<<<dim3(NCHUNK, BATCH), 256>>>();
    carry_kernel<<<BATCH, 256>>>();
    fixup_kernel<<<dim3(NCHUNK, BATCH), 256>>>();
    // h = x + S @ C^T + D*hn1  (M=8192, N=1024, K=64)
    gemm_f16<<<dim3(HIDDEN/128, ROWS/128), 256, TCSMEM>>>(
        Sh, Ch, ROWS, HIDDEN, STATE, STATE,
        h, nullptr, 1, x, nullptr, hn1h, D);
    // FFN
    rmsnorm_w_kernel<<<ROWS/8, 256>>>(h, ln2, hn2h);
    gemm_f16<<<dim3(INTER/128, ROWS/128), 256, TCSMEM>>>(
        hn2h, wgh, ROWS, INTER, HIDDEN, HIDDEN,
        nullptr, gateh, 4, nullptr, nullptr, nullptr, nullptr);
    gemm_f16<<<dim3(INTER/128, ROWS/128), 256, TCSMEM>>>(
        hn2h, wuh, ROWS, INTER, HIDDEN, HIDDEN,
        nullptr, acth, 2, nullptr, gateh, nullptr, nullptr);
    gemm_f16<<<dim3(HIDDEN/128, ROWS/128), 256, TCSMEM>>>(
        acth, wdh, ROWS, HIDDEN, INTER, INTER,
        out, nullptr, 3, h, nullptr, nullptr, nullptr);
}

// round 17
// speedup vs baseline: 1.4909x; 1.0128x over previous
#include <cuda_runtime.h>
#include <cuda_fp16.h>
#include <math.h>
#include <stdint.h>

#define HIDDEN 1024
#define STATE  64
#define INTER  4096
#define BATCH  4
#define SEQ    2048
#define ROWS   (BATCH*SEQ)   // 8192
#define NCHUNK 32
#define CLEN   64            // NCHUNK*CLEN == SEQ
#define KSPLIT 8             // split-K for the U GEMM

// ---------------- scratch (static device allocations; no cudaMalloc) ----------------
__device__ __half g_hn1h[ROWS*HIDDEN];
__device__ float  g_h  [ROWS*HIDDEN];
__device__ __half g_hn2h[ROWS*HIDDEN];
__device__ float  g_U  [KSPLIT*ROWS*STATE];   // split-K partials
__device__ float  g_S  [ROWS*STATE];
__device__ __half g_Sh [ROWS*STATE];
__device__ __half g_gateh[ROWS*INTER];    // gate pre-activation (half)
__device__ __half g_acth[ROWS*INTER];     // silu(gate)*up (half)
__device__ __half g_Bbarh[128*HIDDEN];    // rows 64..127 stay zero (zero-init)
__device__ __half g_Ch[HIDDEN*STATE];
__device__ float  g_AbT [STATE*STATE];    // AbT[j*64+i] = A_bar[i][j]
__device__ float  g_A64T[STATE*STATE];
__device__ float  g_tail [BATCH*NCHUNK*STATE];
__device__ float  g_carry[BATCH*NCHUNK*STATE];
__device__ __half g_wgh[INTER*HIDDEN];    // fp16 weights
__device__ __half g_wuh[INTER*HIDDEN];
__device__ __half g_wdh[HIDDEN*INTER];

// ================= small-matrix helper: 2 rows x 4 cols per thread =================
__device__ __forceinline__ void mm64_24(const float* __restrict__ X,
                                        const float* __restrict__ Y,
                                        int i0, int j0, float v[8])
{
    #pragma unroll
    for (int c = 0; c < 8; c++) v[c] = 0.f;
    #pragma unroll
    for (int lb = 0; lb < 64; lb += 4) {
        float4 x0 = *(const float4*)&X[(i0+0)*64 + lb];
        float4 x1 = *(const float4*)&X[(i0+1)*64 + lb];
        float4 y0 = *(const float4*)&Y[(lb+0)*64 + j0];
        float4 y1 = *(const float4*)&Y[(lb+1)*64 + j0];
        float4 y2 = *(const float4*)&Y[(lb+2)*64 + j0];
        float4 y3 = *(const float4*)&Y[(lb+3)*64 + j0];
        v[0] += x0.x*y0.x + x0.y*y1.x + x0.z*y2.x + x0.w*y3.x;
        v[1] += x0.x*y0.y + x0.y*y1.y + x0.z*y2.y + x0.w*y3.y;
        v[2] += x0.x*y0.z + x0.y*y1.z + x0.z*y2.z + x0.w*y3.z;
        v[3] += x0.x*y0.w + x0.y*y1.w + x0.z*y2.w + x0.w*y3.w;
        v[4] += x1.x*y0.x + x1.y*y1.x + x1.z*y2.x + x1.w*y3.x;
        v[5] += x1.x*y0.y + x1.y*y1.y + x1.z*y2.y + x1.w*y3.y;
        v[6] += x1.x*y0.z + x1.y*y1.z + x1.z*y2.z + x1.w*y3.z;
        v[7] += x1.x*y0.w + x1.y*y1.w + x1.z*y2.w + x1.w*y3.w;
    }
}

// ---------------- prep_fast: dt, mean(dt), Bbar(half)  ----------------
__global__ void __launch_bounds__(256) prep_fast_kernel(
    const float* __restrict__ B, const float* __restrict__ log_dt)
{
    __shared__ float dts[HIDDEN];
    __shared__ float red[256];
    int tid = threadIdx.x;
    float local = 0.f;
    for (int e = tid; e < HIDDEN; e += 256) {
        float d = expf(log_dt[e]);
        dts[e] = d;
        local += d;
    }
    red[tid] = local;
    __syncthreads();
    for (int s = 128; s > 0; s >>= 1) {
        if (tid < s) red[tid] += red[tid + s];
        __syncthreads();
    }
    for (int e = tid; e < STATE*HIDDEN; e += 256)
        g_Bbarh[e] = __float2half(B[e] * dts[e & (HIDDEN - 1)]);
}

// ---------------- prep_mat (512 threads): expm(A*mean_dt), A_bar^64 ----------------
__global__ void __launch_bounds__(512) prep_mat_kernel(
    const float* __restrict__ A, const float* __restrict__ log_dt)
{
    __shared__ __align__(16) float Mm[4096];
    __shared__ __align__(16) float Tb[4096];
    __shared__ __align__(16) float Rb[4096];
    int tid = threadIdx.x;                 // 512

    // recompute mean(dt) independently (keeps this kernel fork-free)
    float local = 0.f;
    for (int e = tid; e < HIDDEN; e += 512) local += expf(log_dt[e]);
    Rb[tid] = local;
    __syncthreads();
    for (int s = 256; s > 0; s >>= 1) {
        if (tid < s) Rb[tid] += Rb[tid + s];
        __syncthreads();
    }
    float md = Rb[0] * (1.f / HIDDEN);
    __syncthreads();

    int i0 = (tid >> 4) * 2;
    int j0 = (tid & 15) * 4;

    for (int e = tid; e < 4096; e += 512) {
        float m = A[e] * md;
        Mm[e] = m; Tb[e] = m;
        Rb[e] = m + ((e >> 6) == (e & 63) ? 1.f : 0.f);
    }
    __syncthreads();

    for (int k = 2; k <= 5; k++) {
        float v[8];
        mm64_24(Tb, Mm, i0, j0, v);
        float inv = 1.f / (float)k;
        __syncthreads();
        #pragma unroll
        for (int r = 0; r < 2; r++)
            #pragma unroll
            for (int c = 0; c < 4; c++) {
                float nv = v[r*4 + c] * inv;
                Tb[(i0+r)*64 + j0 + c] = nv;
                Rb[(i0+r)*64 + j0 + c] += nv;
            }
        __syncthreads();
    }

    #pragma unroll
    for (int r = 0; r < 2; r++)
        #pragma unroll
        for (int c = 0; c < 4; c++)
            g_AbT[(j0+c)*64 + (i0+r)] = Rb[(i0+r)*64 + j0 + c];

    for (int s = 0; s < 6; s++) {
        float v[8];
        mm64_24(Rb, Rb, i0, j0, v);
        __syncthreads();
        #pragma unroll
        for (int r = 0; r < 2; r++)
            #pragma unroll
            for (int c = 0; c < 4; c++)
                Rb[(i0+r)*64 + j0 + c] = v[r*4 + c];
        __syncthreads();
    }
    #pragma unroll
    for (int r = 0; r < 2; r++)
        #pragma unroll
        for (int c = 0; c < 4; c++)
            g_A64T[(j0+c)*64 + (i0+r)] = Rb[(i0+r)*64 + j0 + c];
}

// ---------------- rmsnorm, warp-per-row -> fp16 ----------------
__global__ void __launch_bounds__(256) rmsnorm_w_kernel(
    const float* __restrict__ x, const float* __restrict__ w,
    __half* __restrict__ outh)
{
    int warp = threadIdx.x >> 5, lane = threadIdx.x & 31;
    int row = blockIdx.x * 8 + warp;
    const float4* xr = (const float4*)(x + (size_t)row * HIDDEN);
    const float4* wr = (const float4*)w;

    float4 v[8];
    float ss = 0.f;
    #pragma unroll
    for (int i = 0; i < 8; i++) {
        v[i] = xr[lane + i*32];
        ss += v[i].x*v[i].x + v[i].y*v[i].y + v[i].z*v[i].z + v[i].w*v[i].w;
    }
    #pragma unroll
    for (int o = 16; o > 0; o >>= 1) ss += __shfl_xor_sync(0xffffffffu, ss, o);
    float s = rsqrtf(ss * (1.f / HIDDEN) + 1e-6f);

    #pragma unroll
    for (int i = 0; i < 8; i++) {
        int j = lane + i*32;
        float4 wv = wr[j];
        union { __half2 h[2]; uint2 u; } pk;
        pk.h[0] = __floats2half2_rn(v[i].x*s*wv.x, v[i].y*s*wv.y);
        pk.h[1] = __floats2half2_rn(v[i].z*s*wv.z, v[i].w*s*wv.w);
        *(uint2*)(outh + (size_t)row * HIDDEN + 4*j) = pk.u;
    }
}

// ---------------- fp32 -> fp16: all FFN weights + C in one launch ----------------
__global__ void f2h_weights_kernel(const float* __restrict__ wg,
                                   const float* __restrict__ wu,
                                   const float* __restrict__ wd,
                                   const float* __restrict__ C)
{
    int i = blockIdx.x * 256 + threadIdx.x;
    int stride = gridDim.x * 256;
    const int n2 = INTER*HIDDEN/2;
    const float2* g2 = (const float2*)wg;
    const float2* u2 = (const float2*)wu;
    const float2* d2 = (const float2*)wd;
    __half2* go = (__half2*)g_wgh;
    __half2* uo = (__half2*)g_wuh;
    __half2* dd = (__half2*)g_wdh;
    for (int k = i; k < n2; k += stride) {
        float2 a = g2[k]; go[k] = __floats2half2_rn(a.x, a.y);
        float2 b = u2[k]; uo[k] = __floats2half2_rn(b.x, b.y);
        float2 c = d2[k]; dd[k] = __floats2half2_rn(c.x, c.y);
    }
    const int n2c = HIDDEN*STATE/2;
    const float2* c2 = (const float2*)C;
    __half2* co = (__half2*)g_Ch;
    for (int k = i; k < n2c; k += stride) {
        float2 c = c2[k]; co[k] = __floats2half2_rn(c.x, c.y);
    }
}

// ---------------- chunked scan ----------------
__global__ void local_scan_kernel()
{
    int c = blockIdx.x, b = blockIdx.y;
    size_t ubase = (size_t)(b*SEQ + c*CLEN) * STATE;
    float* sout  = g_S + ubase;

    __shared__ float st[64];
    __shared__ float part[4][64];
    __shared__ float ub[CLEN*64];

    int tid = threadIdx.x;
    int i = tid & 63, p = tid >> 6;

    float a[16];
    #pragma unroll
    for (int jj = 0; jj < 16; jj++) a[jj] = g_AbT[(p*16 + jj)*64 + i];

    for (int e = tid; e < CLEN*64; e += 256) {
        size_t idx = ubase + e;
        float s = 0.f;
        #pragma unroll
        for (int z = 0; z < KSPLIT; z++)
            s += g_U[(size_t)z*ROWS*STATE + idx];
        ub[e] = s;
    }
    if (tid < 64) st[i] = 0.f;
    __syncthreads();

    for (int t = 0; t < CLEN; t++) {
        float acc = 0.f;
        #pragma unroll
        for (int jj = 0; jj < 16; jj++) acc += a[jj] * st[p*16 + jj];
        part[p][i] = acc;
        __syncthreads();
        if (tid < 64) {
            float v = part[0][i] + part[1][i] + part[2][i] + part[3][i] + ub[t*64 + i];
            st[i] = v;
            sout[(size_t)t*STATE + i] = v;
        }
        __syncthreads();
    }
    if (tid < 64) g_tail[(size_t)(b*NCHUNK + c)*STATE + i] = st[i];
}

__global__ void carry_kernel()
{
    int b = blockIdx.x;
    __shared__ float st[64];
    __shared__ float part[4][64];
    __shared__ float tails[NCHUNK*64];

    int tid = threadIdx.x;
    int i = tid & 63, p = tid >> 6;

    float a[16];
    #pragma unroll
    for (int jj = 0; jj < 16; jj++) a[jj] = g_A64T[(p*16 + jj)*64 + i];

    for (int e = tid; e < NCHUNK*64; e += 256)
        tails[e] = g_tail[(size_t)b*NCHUNK*STATE + e];
    if (tid < 64) {
        st[i] = 0.f;
        g_carry[(size_t)b*NCHUNK*STATE + i] = 0.f;
    }
    __syncthreads();

    for (int c = 1; c < NCHUNK; c++) {
        float acc = 0.f;
        #pragma unroll
        for (int jj = 0; jj < 16; jj++) acc += a[jj] * st[p*16 + jj];
        part[p][i] = acc;
        __syncthreads();
        if (tid < 64) {
            float v = part[0][i] + part[1][i] + part[2][i] + part[3][i]
                    + tails[(c-1)*64 + i];
            st[i] = v;
            g_carry[(size_t)(b*NCHUNK + c)*STATE + i] = v;
        }
        __syncthreads();
    }
}

// fixup: S_final = S_local + A^{t+1} carry; writes HALF S for the tensor GEMM
__global__ void fixup_kernel()
{
    int c = blockIdx.x, b = blockIdx.y;
    const float* sin = g_S  + (size_t)(b*SEQ + c*CLEN) * STATE;
    __half* sout     = g_Sh + (size_t)(b*SEQ + c*CLEN) * STATE;

    __shared__ float st[64];
    __shared__ float part[4][64];

    int tid = threadIdx.x;
    int i = tid & 63, p = tid >> 6;

    float a[16];
    #pragma unroll
    for (int jj = 0; jj < 16; jj++) a[jj] = g_AbT[(p*16 + jj)*64 + i];

    if (tid < 64) st[i] = g_carry[(size_t)(b*NCHUNK + c)*STATE + i];
    __syncthreads();

    for (int t = 0; t < CLEN; t++) {
        float acc = 0.f;
        #pragma unroll
        for (int jj = 0; jj < 16; jj++) acc += a[jj] * st[p*16 + jj];
        part[p][i] = acc;
        __syncthreads();
        if (tid < 64) {
            float v = part[0][i] + part[1][i] + part[2][i] + part[3][i];
            st[i] = v;
            sout[(size_t)t*STATE + i] = __float2half(v + sin[(size_t)t*STATE + i]);
        }
        __syncthreads();
    }
}

// ================= fp16 tensor-core GEMM (R7 v3 + split-K): C = A[M,K] @ B[N,K]^T ==========
__device__ __forceinline__ void ldsm4(uint32_t& r0, uint32_t& r1,
                                      uint32_t& r2, uint32_t& r3, uint32_t addr)
{
    asm volatile("ldmatrix.sync.aligned.m8n8.x4.shared.b16 {%0,%1,%2,%3}, [%4];"
                 : "=r"(r0), "=r"(r1), "=r"(r2), "=r"(r3) : "r"(addr));
}
__device__ __forceinline__ void cp16s(uint32_t saddr, const void* g)
{
    asm volatile("cp.async.cg.shared.global [%0], [%1], 16;" :: "r"(saddr), "l"(g));
}
__device__ __forceinline__ void mma_f16(float* d, const uint32_t a[4],
                                        uint32_t b0, uint32_t b1)
{
    asm volatile(
        "mma.sync.aligned.m16n8k16.row.col.f32.f16.f16.f32 "
        "{%0,%1,%2,%3}, {%4,%5,%6,%7}, {%8,%9}, {%0,%1,%2,%3};\n"
        : "+f"(d[0]), "+f"(d[1]), "+f"(d[2]), "+f"(d[3])
        : "r"(a[0]), "r"(a[1]), "r"(a[2]), "r"(a[3]), "r"(b0), "r"(b1));
}

#define STAGE_B 20480        // bytes per stage (A 10240 + B 10240), row pitch 80B
#define TCSMEM  (3*STAGE_B)  // 61440

// K = compute-K per blockIdx.z slice; kld = row stride of A and B in elements.
// modes: 0 outf[z*M*N + idx]=acc; 1 outf = res + acc + dvec[col]*extrah(half);
//        2 outh = half(silu(resh)*acc); 3 outf = res + acc; 4 outh = half(acc)
__global__ void __launch_bounds__(256) gemm_f16(
    const __half* __restrict__ A, const __half* __restrict__ Bm,
    int M, int N, int K, int kld, float* __restrict__ outf, __half* __restrict__ outh,
    int mode, const float* __restrict__ res, const __half* __restrict__ resh,
    const __half* __restrict__ extrah, const float* __restrict__ dvec)
{
    extern __shared__ __align__(16) char smem[];
    uint32_t smBase = (uint32_t)__cvta_generic_to_shared(smem);
    int tid = threadIdx.x;
    int m0 = blockIdx.y * 128, n0 = blockIdx.x * 128;
    int koff = blockIdx.z * K;

    int lr = tid >> 1, lc = (tid & 1) * 2;
    const __half* Ag = A  + (size_t)(m0 + lr) * kld + koff + lc*8;
    const __half* Bg = Bm + (size_t)(n0 + lr) * kld + koff + lc*8;
    uint32_t aDst = smBase + lr*80 + lc*16;
    uint32_t bDst = smBase + 10240 + lr*80 + lc*16;

    int lane = tid & 31, warp = tid >> 5;
    int wm = warp & 1, wn = warp >> 1;
    int gid = lane >> 2, tig = lane & 3;

    uint32_t aFrag = smBase
        + (uint32_t)(wm*64 + (lane & 7) + ((lane >> 3) & 1)*8) * 80
        + ((lane >> 4) & 1) * 16;
    uint32_t bFrag = smBase + 10240
        + (uint32_t)(wn*32 + ((lane >> 4) & 1)*8 + (lane & 7)) * 80
        + ((lane >> 3) & 1) * 16;

    float acc[4][4][4];
    #pragma unroll
    for (int mt = 0; mt < 4; mt++)
        #pragma unroll
        for (int nt = 0; nt < 4; nt++)
            #pragma unroll
            for (int r = 0; r < 4; r++) acc[mt][nt][r] = 0.f;

    int NT = K >> 5;

    #define LOAD_STAGE(kt, s) do {                                           \
        uint32_t off_ = (uint32_t)(s) * STAGE_B;                             \
        const __half* ga_ = Ag + (size_t)(kt)*32;                            \
        const __half* gb_ = Bg + (size_t)(kt)*32;                            \
        cp16s(aDst + off_,      ga_);                                        \
        cp16s(aDst + off_ + 16, ga_ + 8);                                    \
        cp16s(bDst + off_,      gb_);                                        \
        cp16s(bDst + off_ + 16, gb_ + 8);                                    \
        asm volatile("cp.async.commit_group;\n");                            \
    } while (0)

    LOAD_STAGE(0, 0);
    if (NT > 1) LOAD_STAGE(1, 1);

    int st = 0, ld = 2;
    for (int kt = 0; kt < NT; kt++) {
        if (kt + 1 < NT) asm volatile("cp.async.wait_group 1;\n");
        else             asm volatile("cp.async.wait_group 0;\n");
        __syncthreads();

        if (kt + 2 < NT) {
            LOAD_STAGE(kt + 2, ld);
            ld = (ld == 2) ? 0 : ld + 1;
        }

        uint32_t soff = (uint32_t)st * STAGE_B;
        st = (st == 2) ? 0 : st + 1;

        #pragma unroll
        for (int ks = 0; ks < 2; ks++) {
            uint32_t bb[2][4];
            #pragma unroll
            for (int p = 0; p < 2; p++)
                ldsm4(bb[p][0], bb[p][1], bb[p][2], bb[p][3],
                      bFrag + soff + (uint32_t)p*16*80 + ks*32);
            #pragma unroll
            for (int mt = 0; mt < 4; mt++) {
                uint32_t aa[4];
                ldsm4(aa[0], aa[1], aa[2], aa[3],
                      aFrag + soff + (uint32_t)mt*16*80 + ks*32);
                mma_f16(acc[mt][0], aa, bb[0][0], bb[0][1]);
                mma_f16(acc[mt][1], aa, bb[0][2], bb[0][3]);
                mma_f16(acc[mt][2], aa, bb[1][0], bb[1][1]);
                mma_f16(acc[mt][3], aa, bb[1][2], bb[1][3]);
            }
        }
    }
    #undef LOAD_STAGE

    float* outz = outf + (mode == 0 ? (size_t)blockIdx.z * M * N : 0);

    // epilogue (col-guarded for N < 128 tiles)
    #pragma unroll
    for (int mt = 0; mt < 4; mt++) {
        #pragma unroll
        for (int nt = 0; nt < 4; nt++) {
            int row0 = m0 + wm*64 + mt*16 + gid;
            int col0 = n0 + wn*32 + nt*8 + tig*2;
            if (col0 >= N) continue;
            #pragma unroll
            for (int half = 0; half < 2; half++) {
                int row = row0 + half*8;
                size_t idx = (size_t)row * N + col0;
                float v0 = acc[mt][nt][half*2 + 0];
                float v1 = acc[mt][nt][half*2 + 1];
                if (mode == 1) {
                    float2 r2 = *(const float2*)(res + idx);
                    float2 e2 = __half22float2(*(const __half2*)(extrah + idx));
                    v0 = r2.x + v0 + dvec[col0]   * e2.x;
                    v1 = r2.y + v1 + dvec[col0+1] * e2.y;
                    *(float2*)(outf + idx) = make_float2(v0, v1);
                } else if (mode == 2) {
                    float2 g2 = __half22float2(*(const __half2*)(resh + idx));
                    v0 = v0 * (g2.x / (1.f + __expf(-g2.x)));
                    v1 = v1 * (g2.y / (1.f + __expf(-g2.y)));
                    *(__half2*)(outh + idx) = __floats2half2_rn(v0, v1);
                } else if (mode == 3) {
                    float2 r2 = *(const float2*)(res + idx);
                    *(float2*)(outf + idx) = make_float2(v0 + r2.x, v1 + r2.y);
                } else if (mode == 4) {
                    *(__half2*)(outh + idx) = __floats2half2_rn(v0, v1);
                } else {
                    *(float2*)(outz + idx) = make_float2(v0, v1);
                }
            }
        }
    }
}

// ---------------- launch ----------------
extern "C" void kernel_launch(void* const* d_in, const int* in_sizes, int n_in,
                              void* d_out, int out_size)
{
    const float* x      = (const float*)d_in[0];
    const float* A      = (const float*)d_in[1];
    const float* B      = (const float*)d_in[2];
    const float* C      = (const float*)d_in[3];
    const float* D      = (const float*)d_in[4];
    const float* log_dt = (const float*)d_in[5];
    const float* w_gate = (const float*)d_in[6];
    const float* w_up   = (const float*)d_in[7];
    const float* w_down = (const float*)d_in[8];
    const float* ln1    = (const float*)d_in[9];
    const float* ln2    = (const float*)d_in[10];
    float* out = (float*)d_out;

    float *h, *U;
    __half *hn1h, *hn2h, *gateh, *acth, *Bbarh, *Ch, *Sh, *wgh, *wuh, *wdh;
    cudaGetSymbolAddress((void**)&hn1h,  g_hn1h);
    cudaGetSymbolAddress((void**)&h,     g_h);
    cudaGetSymbolAddress((void**)&hn2h,  g_hn2h);
    cudaGetSymbolAddress((void**)&U,     g_U);
    cudaGetSymbolAddress((void**)&gateh, g_gateh);
    cudaGetSymbolAddress((void**)&acth,  g_acth);
    cudaGetSymbolAddress((void**)&Bbarh, g_Bbarh);
    cudaGetSymbolAddress((void**)&Ch,    g_Ch);
    cudaGetSymbolAddress((void**)&Sh,    g_Sh);
    cudaGetSymbolAddress((void**)&wgh,   g_wgh);
    cudaGetSymbolAddress((void**)&wuh,   g_wuh);
    cudaGetSymbolAddress((void**)&wdh,   g_wdh);

    cudaFuncSetAttribute(gemm_f16, cudaFuncAttributeMaxDynamicSharedMemorySize, TCSMEM);

    // one-time side streams + events (host objects; no device memory)
    static cudaStream_t s2 = nullptr, s3 = nullptr;
    static cudaEvent_t evF = nullptr, ev2 = nullptr, ev3 = nullptr;
    if (s2 == nullptr) {
        cudaStreamCreateWithFlags(&s2, cudaStreamNonBlocking);
        cudaStreamCreateWithFlags(&s3, cudaStreamNonBlocking);
        cudaEventCreateWithFlags(&evF, cudaEventDisableTiming);
        cudaEventCreateWithFlags(&ev2, cudaEventDisableTiming);
        cudaEventCreateWithFlags(&ev3, cudaEventDisableTiming);
    }

    // fork: s2 = weight/C conversion (needed by S@C); s3 = expm chain (needed by scan)
    cudaEventRecord(evF, 0);
    cudaStreamWaitEvent(s2, evF, 0);
    f2h_weights_kernel<<<1024, 256, 0, s2>>>(w_gate, w_up, w_down, C);
    cudaEventRecord(ev2, s2);

    cudaStreamWaitEvent(s3, evF, 0);
    prep_mat_kernel<<<1, 512, 0, s3>>>(A, log_dt);
    cudaEventRecord(ev3, s3);

    // main: fast prep + rmsnorm1 + U GEMM (none of these need expm or weights)
    prep_fast_kernel<<<1, 256>>>(B, log_dt);
    rmsnorm_w_kernel<<<ROWS/8, 256>>>(x, ln1, hn1h);
    gemm_f16<<<dim3(1, ROWS/128, KSPLIT), 256, TCSMEM>>>(
        hn1h, Bbarh, ROWS, STATE, HIDDEN/KSPLIT, HIDDEN,
        U, nullptr, 0, nullptr, nullptr, nullptr, nullptr);

    // scan chain needs g_AbT / g_A64T
    cudaStreamWaitEvent(0, ev3, 0);
    local_scan_kernel<<<dim3(NCHUNK, BATCH), 256>>>();
    carry_kernel<<<BATCH, 256>>>();
    fixup_kernel<<<dim3(NCHUNK, BATCH), 256>>>();

    // S@C needs g_Ch (from f2h)
    cudaStreamWaitEvent(0, ev2, 0);
    gemm_f16<<<dim3(HIDDEN/128, ROWS/128), 256, TCSMEM>>>(
        Sh, Ch, ROWS, HIDDEN, STATE, STATE,
        h, nullptr, 1, x, nullptr, hn1h, D);
    // FFN
    rmsnorm_w_kernel<<<ROWS/8, 256>>>(h, ln2, hn2h);
    gemm_f16<<<dim3(INTER/128, ROWS/128), 256, TCSMEM>>>(
        hn2h, wgh, ROWS, INTER, HIDDEN, HIDDEN,
        nullptr, gateh, 4, nullptr, nullptr, nullptr, nullptr);
    gemm_f16<<<dim3(INTER/128, ROWS/128), 256, TCSMEM>>>(
        hn2h, wuh, ROWS, INTER, HIDDEN, HIDDEN,
        nullptr, acth, 2, nullptr, gateh, nullptr, nullptr);
    gemm_f16<<<dim3(HIDDEN/128, ROWS/128), 256, TCSMEM>>>(
        acth, wdh, ROWS, HIDDEN, INTER, INTER,
        out, nullptr, 3, h, nullptr, nullptr, nullptr);
}